// round 4
// baseline (speedup 1.0000x reference)
#include <cuda_runtime.h>
#include <cstdint>

#define BB 2
#define TT 2048
#define HH 16
#define DD 64
#define DM 1024
#define BT (BB*TT)      // 4096
#define BHD (BB*HH)     // 32

// ---------------- static scratch (no allocations allowed) ----------------
__device__ float g_Q[(size_t)BT*DM];   // 16 MB
__device__ float g_K[(size_t)BT*DM];   // 16 MB
__device__ float g_V[(size_t)BT*DM];   // 16 MB
__device__ float g_R[BHD*TT];          // 1/Z per (b,h,tk)
__device__ float g_C[BHD*TT];          // colsum per (b,h,tq)

// ---------------- fast exp on the FMA pipe (avoid MUFU throughput wall) ----
__device__ __forceinline__ float fast_exp(float x) {
    // clamp: scores/8 are ~N(0,1); clamp keeps exponent arithmetic safe always
    x = fminf(fmaxf(x, -60.f), 60.f);
    float y = x * 1.4426950408889634f;
    float n = rintf(y);
    float f = y - n;
    float p = 1.3333558146428443e-3f;
    p = fmaf(p, f, 9.618129842126066e-3f);
    p = fmaf(p, f, 5.550410866482158e-2f);
    p = fmaf(p, f, 2.402265069591007e-1f);
    p = fmaf(p, f, 6.931471805599453e-1f);
    p = fmaf(p, f, 1.0f);
    return p * __int_as_float(((int)n + 127) << 23);
}

// ---------------- generic 128x128 tiled fp32 GEMM: C = (A*scale) @ W + bias -
// A: [M,K] row-major, W: [K,N] row-major, bias: [N]
// scale (optional): per-(m, k-head) multiplier: scale[((m/T)*H + k/D)*T + m%T]
__global__ void __launch_bounds__(256) gemm_bias(
    const float* __restrict__ A, const float* __restrict__ W,
    const float* __restrict__ bias, const float* __restrict__ scale,
    float* __restrict__ Cout, int M, int N, int K)
{
    __shared__ __align__(16) float As[8][132];   // k-major (transposed), padded
    __shared__ __align__(16) float Bs[8][128];

    const int tid = threadIdx.x;
    const int tx = tid & 15, ty = tid >> 4;
    const int m0 = blockIdx.y * 128, n0 = blockIdx.x * 128;

    float acc[8][8];
    #pragma unroll
    for (int i = 0; i < 8; i++)
        #pragma unroll
        for (int j = 0; j < 8; j++) acc[i][j] = 0.f;

    const int arow = tid >> 1;           // 0..127
    const int akq  = (tid & 1) * 4;      // 0 or 4
    const int bk   = tid >> 5;           // 0..7
    const int bn   = (tid & 31) * 4;     // 0..124

    for (int kb = 0; kb < K; kb += 8) {
        float4 av = *(const float4*)&A[(size_t)(m0 + arow) * K + kb + akq];
        if (scale) {
            int m = m0 + arow;
            float s = scale[(((m / TT) * HH) + (kb / DD)) * TT + (m % TT)];
            av.x *= s; av.y *= s; av.z *= s; av.w *= s;
        }
        As[akq + 0][arow] = av.x; As[akq + 1][arow] = av.y;
        As[akq + 2][arow] = av.z; As[akq + 3][arow] = av.w;
        *(float4*)&Bs[bk][bn] = *(const float4*)&W[(size_t)(kb + bk) * N + n0 + bn];
        __syncthreads();

        #pragma unroll
        for (int kk = 0; kk < 8; kk++) {
            float a[8], b[8];
            *(float4*)&a[0] = *(const float4*)&As[kk][ty * 8];
            *(float4*)&a[4] = *(const float4*)&As[kk][ty * 8 + 4];
            *(float4*)&b[0] = *(const float4*)&Bs[kk][tx * 8];
            *(float4*)&b[4] = *(const float4*)&Bs[kk][tx * 8 + 4];
            #pragma unroll
            for (int i = 0; i < 8; i++)
                #pragma unroll
                for (int j = 0; j < 8; j++)
                    acc[i][j] = fmaf(a[i], b[j], acc[i][j]);
        }
        __syncthreads();
    }

    float bv[8];
    #pragma unroll
    for (int j = 0; j < 8; j++) bv[j] = bias[n0 + tx * 8 + j];
    #pragma unroll
    for (int i = 0; i < 8; i++) {
        size_t off = (size_t)(m0 + ty * 8 + i) * N + n0 + tx * 8;
        *(float4*)&Cout[off] = make_float4(acc[i][0] + bv[0], acc[i][1] + bv[1],
                                           acc[i][2] + bv[2], acc[i][3] + bv[3]);
        *(float4*)&Cout[off + 4] = make_float4(acc[i][4] + bv[4], acc[i][5] + bv[5],
                                               acc[i][6] + bv[6], acc[i][7] + bv[7]);
    }
}

// ---- shared helper: load a 128x32 chunk of rows, k-major transposed, to smem
// 128 rows x 32 floats = 128 x 8 float4 slots = 1024 slots; 256 threads -> j<4
__device__ __forceinline__ void load_chunk_T(
    float dst[32][132], const float* __restrict__ src, int row0, int kh, int tid)
{
    #pragma unroll
    for (int j = 0; j < 4; j++) {
        int pos = j * 256 + tid;     // 0..1023
        int row = pos >> 3;          // 0..127
        int kq  = (pos & 7) * 4;     // 0..28
        float4 v = *(const float4*)&src[(size_t)(row0 + row) * DM + kh * 32 + kq];
        dst[kq + 0][row] = v.x; dst[kq + 1][row] = v.y;
        dst[kq + 2][row] = v.z; dst[kq + 3][row] = v.w;
    }
}

// ---------------- pass 1: Z[tk] = sum_tq exp(s/8) ; store R = 1/Z -----------
// CTA: one (b,h), 128 tk rows, sweeps all 2048 tq.
__global__ void __launch_bounds__(256) attn_z()
{
    __shared__ __align__(16) float kT[32][132];
    __shared__ __align__(16) float qT[32][132];
    __shared__ float Zs[128];

    const int tid = threadIdx.x;
    const int tx = tid & 15, ty = tid >> 4;
    const int bh = blockIdx.y;
    const int b = bh >> 4, h = bh & 15;
    const int tk0 = blockIdx.x * 128;

    const float* Qb = g_Q + (size_t)b * TT * DM + h * DD;
    const float* Kb = g_K + (size_t)b * TT * DM + h * DD;

    if (tid < 128) Zs[tid] = 0.f;

    float zacc[8];
    #pragma unroll
    for (int i = 0; i < 8; i++) zacc[i] = 0.f;

    for (int tqc = 0; tqc < 16; tqc++) {
        float acc[8][8];
        #pragma unroll
        for (int i = 0; i < 8; i++)
            #pragma unroll
            for (int j = 0; j < 8; j++) acc[i][j] = 0.f;

        #pragma unroll
        for (int kh = 0; kh < 2; kh++) {
            __syncthreads();
            load_chunk_T(kT, Kb, tk0, kh, tid);
            load_chunk_T(qT, Qb, tqc * 128, kh, tid);
            __syncthreads();
            #pragma unroll
            for (int kk = 0; kk < 32; kk++) {
                float a[8], q[8];
                *(float4*)&a[0] = *(const float4*)&kT[kk][ty * 8];
                *(float4*)&a[4] = *(const float4*)&kT[kk][ty * 8 + 4];
                *(float4*)&q[0] = *(const float4*)&qT[kk][tx * 8];
                *(float4*)&q[4] = *(const float4*)&qT[kk][tx * 8 + 4];
                #pragma unroll
                for (int i = 0; i < 8; i++)
                    #pragma unroll
                    for (int j = 0; j < 8; j++)
                        acc[i][j] = fmaf(a[i], q[j], acc[i][j]);
            }
        }
        #pragma unroll
        for (int i = 0; i < 8; i++)
            #pragma unroll
            for (int j = 0; j < 8; j++)
                zacc[i] += fast_exp(acc[i][j] * 0.125f);
    }

    __syncthreads();
    #pragma unroll
    for (int i = 0; i < 8; i++) atomicAdd(&Zs[ty * 8 + i], zacc[i]);
    __syncthreads();
    if (tid < 128) g_R[bh * TT + tk0 + tid] = 1.0f / Zs[tid];
}

// ---------------- pass 2: colsum[tq] = sum_tk exp(s/8) * R[tk] --------------
// CTA: one (b,h), 128 tq columns, sweeps all 2048 tk. No cross-CTA atomics.
__global__ void __launch_bounds__(256) attn_colsum()
{
    __shared__ __align__(16) float kT[32][132];
    __shared__ __align__(16) float qT[32][132];
    __shared__ float Cs[128];

    const int tid = threadIdx.x;
    const int tx = tid & 15, ty = tid >> 4;
    const int bh = blockIdx.y;
    const int b = bh >> 4, h = bh & 15;
    const int tq0 = blockIdx.x * 128;

    const float* Qb = g_Q + (size_t)b * TT * DM + h * DD;
    const float* Kb = g_K + (size_t)b * TT * DM + h * DD;

    if (tid < 128) Cs[tid] = 0.f;

    float csum[8];
    #pragma unroll
    for (int j = 0; j < 8; j++) csum[j] = 0.f;

    for (int tkc = 0; tkc < 16; tkc++) {
        float acc[8][8];
        #pragma unroll
        for (int i = 0; i < 8; i++)
            #pragma unroll
            for (int j = 0; j < 8; j++) acc[i][j] = 0.f;

        #pragma unroll
        for (int kh = 0; kh < 2; kh++) {
            __syncthreads();
            load_chunk_T(kT, Kb, tkc * 128, kh, tid);
            load_chunk_T(qT, Qb, tq0, kh, tid);
            __syncthreads();
            #pragma unroll
            for (int kk = 0; kk < 32; kk++) {
                float a[8], q[8];
                *(float4*)&a[0] = *(const float4*)&kT[kk][ty * 8];
                *(float4*)&a[4] = *(const float4*)&kT[kk][ty * 8 + 4];
                *(float4*)&q[0] = *(const float4*)&qT[kk][tx * 8];
                *(float4*)&q[4] = *(const float4*)&qT[kk][tx * 8 + 4];
                #pragma unroll
                for (int i = 0; i < 8; i++)
                    #pragma unroll
                    for (int j = 0; j < 8; j++)
                        acc[i][j] = fmaf(a[i], q[j], acc[i][j]);
            }
        }
        float r[8];
        #pragma unroll
        for (int i = 0; i < 8; i++) r[i] = g_R[bh * TT + tkc * 128 + ty * 8 + i];
        #pragma unroll
        for (int i = 0; i < 8; i++)
            #pragma unroll
            for (int j = 0; j < 8; j++)
                csum[j] = fmaf(fast_exp(acc[i][j] * 0.125f), r[i], csum[j]);
    }

    __syncthreads();
    #pragma unroll
    for (int j = 0; j < 8; j++) atomicAdd(&Cs[tx * 8 + j], csum[j]);
    __syncthreads();
    if (tid < 128) g_C[bh * TT + tq0 + tid] = Cs[tid];
}

// ---------------- launch -----------------------------------------------------
extern "C" void kernel_launch(void* const* d_in, const int* in_sizes, int n_in,
                              void* d_out, int out_size)
{
    const float* x  = (const float*)d_in[0];
    const float* Wq = (const float*)d_in[1];
    const float* bq = (const float*)d_in[2];
    const float* Wk = (const float*)d_in[3];
    const float* bk = (const float*)d_in[4];
    const float* Wv = (const float*)d_in[5];
    const float* bv = (const float*)d_in[6];
    const float* Wo = (const float*)d_in[7];
    const float* bo = (const float*)d_in[8];
    float* out = (float*)d_out;

    float *Qp, *Kp, *Vp, *Cp;
    cudaGetSymbolAddress((void**)&Qp, g_Q);
    cudaGetSymbolAddress((void**)&Kp, g_K);
    cudaGetSymbolAddress((void**)&Vp, g_V);
    cudaGetSymbolAddress((void**)&Cp, g_C);

    dim3 gproj(DM / 128, BT / 128);   // (8, 32)

    gemm_bias<<<gproj, 256>>>(x, Wq, bq, nullptr, Qp, BT, DM, DM);
    gemm_bias<<<gproj, 256>>>(x, Wk, bk, nullptr, Kp, BT, DM, DM);
    gemm_bias<<<gproj, 256>>>(x, Wv, bv, nullptr, Vp, BT, DM, DM);
    attn_z<<<dim3(TT / 128, BHD), 256>>>();
    attn_colsum<<<dim3(TT / 128, BHD), 256>>>();
    gemm_bias<<<gproj, 256>>>(Vp, Wo, bo, Cp, out, BT, DM, DM);
}

// round 6
// speedup vs baseline: 1.8513x; 1.8513x over previous
#include <cuda_runtime.h>
#include <cstdint>

#define BB 2
#define TT 2048
#define HH 16
#define DD 64
#define DM 1024
#define BT (BB*TT)      // 4096
#define BHD (BB*HH)     // 32

// ---------------- static scratch ----------------
__device__ float g_Q[(size_t)BT*DM];   // 16 MB
__device__ float g_K[(size_t)BT*DM];   // 16 MB
__device__ float g_V[(size_t)BT*DM];   // 16 MB
__device__ float g_R[BHD*TT];          // 1/Z per (b,h,tk)
__device__ float g_C[BHD*TT];          // colsum per (b,h,tq)

// ---------------- helpers ----------------
__device__ __forceinline__ uint32_t f2tf(float x) {
    uint32_t r;
    asm("cvt.rna.tf32.f32 %0, %1;" : "=r"(r) : "f"(x));
    return r;
}

__device__ __forceinline__ void mma8(float c[4],
    uint32_t a0, uint32_t a1, uint32_t a2, uint32_t a3,
    uint32_t b0, uint32_t b1)
{
    asm volatile(
        "mma.sync.aligned.m16n8k8.row.col.f32.tf32.tf32.f32 "
        "{%0,%1,%2,%3}, {%4,%5,%6,%7}, {%8,%9}, {%0,%1,%2,%3};"
        : "+f"(c[0]), "+f"(c[1]), "+f"(c[2]), "+f"(c[3])
        : "r"(a0), "r"(a1), "r"(a2), "r"(a3), "r"(b0), "r"(b1));
}

__device__ __forceinline__ float fast_exp(float x) {
    x = fminf(fmaxf(x, -60.f), 60.f);
    float y = x * 1.4426950408889634f;
    float n = rintf(y);
    float f = y - n;
    float p = 1.3333558146428443e-3f;
    p = fmaf(p, f, 9.618129842126066e-3f);
    p = fmaf(p, f, 5.550410866482158e-2f);
    p = fmaf(p, f, 2.402265069591007e-1f);
    p = fmaf(p, f, 6.931471805599453e-1f);
    p = fmaf(p, f, 1.0f);
    return p * __int_as_float(((int)n + 127) << 23);
}

// ============ tf32 tensor GEMM: C = (A*scale) @ W + bias ===================
// A: [M,K] fp32 row-major, W: [K,N] fp32 row-major, bias: [N]
// scale (optional): per-(m, head(k)) multiplier: scale[((m/T)*H + k/D)*T + m%T]
// CTA 128x128, 8 warps (2m x 4n), warp tile 64x32, k-chunk 32.
__global__ void __launch_bounds__(256) gemm_tf32(
    const float* __restrict__ A, const float* __restrict__ W,
    const float* __restrict__ bias, const float* __restrict__ scale,
    float* __restrict__ Cout, int M, int N, int K)
{
    __shared__ uint32_t As[32][132];   // [k][m]
    __shared__ uint32_t Bs[128][33];   // [n][k] (W transposed)

    const int tid = threadIdx.x, lane = tid & 31, wid = tid >> 5;
    const int grp = lane >> 2, t4 = lane & 3;
    const int wm = wid >> 2, wn = wid & 3;
    const int m0 = blockIdx.y * 128, n0 = blockIdx.x * 128;

    float c[4][4][4];
    #pragma unroll
    for (int mi = 0; mi < 4; mi++)
        #pragma unroll
        for (int ni = 0; ni < 4; ni++)
            #pragma unroll
            for (int r = 0; r < 4; r++) c[mi][ni][r] = 0.f;

    const int am = tid >> 1;            // A row within tile (0..127)
    const int ak = (tid & 1) * 16;      // A col base (0 or 16)
    const int bk = tid >> 3;            // W row (k, 0..31)
    const int bn = (tid & 7) * 4;       // W col base, +32*i

    for (int kb = 0; kb < K; kb += 32) {
        float sc = 1.f;
        if (scale) {
            int mg = m0 + am;
            sc = scale[(((mg / TT) * HH) + (kb / DD)) * TT + (mg % TT)];
        }
        #pragma unroll
        for (int i = 0; i < 4; i++) {
            float4 v = *(const float4*)&A[(size_t)(m0 + am) * K + kb + ak + i * 4];
            if (scale) { v.x *= sc; v.y *= sc; v.z *= sc; v.w *= sc; }
            As[ak + i * 4 + 0][am] = f2tf(v.x);
            As[ak + i * 4 + 1][am] = f2tf(v.y);
            As[ak + i * 4 + 2][am] = f2tf(v.z);
            As[ak + i * 4 + 3][am] = f2tf(v.w);
        }
        #pragma unroll
        for (int i = 0; i < 4; i++) {
            float4 w = *(const float4*)&W[(size_t)(kb + bk) * N + n0 + bn + i * 32];
            Bs[bn + i * 32 + 0][bk] = f2tf(w.x);
            Bs[bn + i * 32 + 1][bk] = f2tf(w.y);
            Bs[bn + i * 32 + 2][bk] = f2tf(w.z);
            Bs[bn + i * 32 + 3][bk] = f2tf(w.w);
        }
        __syncthreads();

        #pragma unroll
        for (int ks = 0; ks < 4; ks++) {
            const int k0 = ks * 8;
            uint32_t a[4][4], b[4][2];
            #pragma unroll
            for (int mi = 0; mi < 4; mi++) {
                int m = wm * 64 + mi * 16 + grp;
                a[mi][0] = As[k0 + t4][m];
                a[mi][1] = As[k0 + t4][m + 8];
                a[mi][2] = As[k0 + t4 + 4][m];
                a[mi][3] = As[k0 + t4 + 4][m + 8];
            }
            #pragma unroll
            for (int ni = 0; ni < 4; ni++) {
                int n = wn * 32 + ni * 8 + grp;
                b[ni][0] = Bs[n][k0 + t4];
                b[ni][1] = Bs[n][k0 + t4 + 4];
            }
            #pragma unroll
            for (int mi = 0; mi < 4; mi++)
                #pragma unroll
                for (int ni = 0; ni < 4; ni++)
                    mma8(c[mi][ni], a[mi][0], a[mi][1], a[mi][2], a[mi][3],
                         b[ni][0], b[ni][1]);
        }
        __syncthreads();
    }

    #pragma unroll
    for (int mi = 0; mi < 4; mi++) {
        int r0 = m0 + wm * 64 + mi * 16 + grp;
        #pragma unroll
        for (int ni = 0; ni < 4; ni++) {
            int cb = n0 + wn * 32 + ni * 8 + 2 * t4;
            float b0 = bias[cb], b1 = bias[cb + 1];
            float2 v0 = make_float2(c[mi][ni][0] + b0, c[mi][ni][1] + b1);
            float2 v1 = make_float2(c[mi][ni][2] + b0, c[mi][ni][3] + b1);
            *(float2*)&Cout[(size_t)r0 * N + cb]       = v0;
            *(float2*)&Cout[(size_t)(r0 + 8) * N + cb] = v1;
        }
    }
}

// ---- load a 128-row x 32-d chunk, k-major transposed, tf32 bits into smem --
__device__ __forceinline__ void load_chunk_tf(
    uint32_t dst[32][132], const float* __restrict__ src, int row0, int kh, int tid)
{
    #pragma unroll
    for (int j = 0; j < 4; j++) {
        int pos = j * 256 + tid;     // 0..1023
        int row = pos >> 3;          // 0..127
        int kq  = (pos & 7) * 4;     // 0..28
        float4 v = *(const float4*)&src[(size_t)(row0 + row) * DM + kh * 32 + kq];
        dst[kq + 0][row] = f2tf(v.x); dst[kq + 1][row] = f2tf(v.y);
        dst[kq + 2][row] = f2tf(v.z); dst[kq + 3][row] = f2tf(v.w);
    }
}

// ---- shared mma inner step for the score tile: acc s[tk 128][tq 128] ------
__device__ __forceinline__ void score_mma_chunk(
    float c[4][4][4], const uint32_t Ks[32][132], const uint32_t Qs[32][132],
    int wm, int wn, int grp, int t4)
{
    #pragma unroll
    for (int ks = 0; ks < 4; ks++) {
        const int k0 = ks * 8;
        uint32_t a[4][4], b[4][2];
        #pragma unroll
        for (int mi = 0; mi < 4; mi++) {
            int m = wm * 64 + mi * 16 + grp;
            a[mi][0] = Ks[k0 + t4][m];
            a[mi][1] = Ks[k0 + t4][m + 8];
            a[mi][2] = Ks[k0 + t4 + 4][m];
            a[mi][3] = Ks[k0 + t4 + 4][m + 8];
        }
        #pragma unroll
        for (int ni = 0; ni < 4; ni++) {
            int n = wn * 32 + ni * 8 + grp;
            b[ni][0] = Qs[k0 + t4][n];
            b[ni][1] = Qs[k0 + t4 + 4][n];
        }
        #pragma unroll
        for (int mi = 0; mi < 4; mi++)
            #pragma unroll
            for (int ni = 0; ni < 4; ni++)
                mma8(c[mi][ni], a[mi][0], a[mi][1], a[mi][2], a[mi][3],
                     b[ni][0], b[ni][1]);
    }
}

// ============ pass 1: Z[tk] = sum_tq exp(s/8); R = 1/Z =====================
__global__ void __launch_bounds__(256) attn_z_mma()
{
    __shared__ uint32_t Ks[32][132];
    __shared__ uint32_t Qs[32][132];
    __shared__ float Zs[128];

    const int tid = threadIdx.x, lane = tid & 31, wid = tid >> 5;
    const int grp = lane >> 2, t4 = lane & 3;
    const int wm = wid >> 2, wn = wid & 3;
    const int bh = blockIdx.y, b = bh >> 4, h = bh & 15;
    const int tk0 = blockIdx.x * 128;

    const float* Qb = g_Q + (size_t)b * TT * DM + h * DD;
    const float* Kb = g_K + (size_t)b * TT * DM + h * DD;

    if (tid < 128) Zs[tid] = 0.f;

    float zacc[4][2];
    #pragma unroll
    for (int mi = 0; mi < 4; mi++) { zacc[mi][0] = 0.f; zacc[mi][1] = 0.f; }

    for (int tqc = 0; tqc < 16; tqc++) {
        float c[4][4][4];
        #pragma unroll
        for (int mi = 0; mi < 4; mi++)
            #pragma unroll
            for (int ni = 0; ni < 4; ni++)
                #pragma unroll
                for (int r = 0; r < 4; r++) c[mi][ni][r] = 0.f;

        #pragma unroll
        for (int kh = 0; kh < 2; kh++) {
            __syncthreads();
            load_chunk_tf(Ks, Kb, tk0, kh, tid);
            load_chunk_tf(Qs, Qb, tqc * 128, kh, tid);
            __syncthreads();
            score_mma_chunk(c, Ks, Qs, wm, wn, grp, t4);
        }
        #pragma unroll
        for (int mi = 0; mi < 4; mi++)
            #pragma unroll
            for (int ni = 0; ni < 4; ni++) {
                zacc[mi][0] += fast_exp(c[mi][ni][0] * 0.125f)
                             + fast_exp(c[mi][ni][1] * 0.125f);
                zacc[mi][1] += fast_exp(c[mi][ni][2] * 0.125f)
                             + fast_exp(c[mi][ni][3] * 0.125f);
            }
    }

    __syncthreads();
    #pragma unroll
    for (int mi = 0; mi < 4; mi++)
        #pragma unroll
        for (int hf = 0; hf < 2; hf++) {
            float v = zacc[mi][hf];
            v += __shfl_xor_sync(0xffffffffu, v, 1);
            v += __shfl_xor_sync(0xffffffffu, v, 2);
            if (t4 == 0) atomicAdd(&Zs[wm * 64 + mi * 16 + grp + hf * 8], v);
        }
    __syncthreads();
    if (tid < 128) g_R[bh * TT + tk0 + tid] = 1.0f / Zs[tid];
}

// ============ pass 2: colsum[tq] = sum_tk exp(s/8) * R[tk] =================
__global__ void __launch_bounds__(256) attn_cs_mma()
{
    __shared__ uint32_t Ks[32][132];
    __shared__ uint32_t Qs[32][132];
    __shared__ float Rs[128];
    __shared__ float Cs[128];

    const int tid = threadIdx.x, lane = tid & 31, wid = tid >> 5;
    const int grp = lane >> 2, t4 = lane & 3;
    const int wm = wid >> 2, wn = wid & 3;
    const int bh = blockIdx.y, b = bh >> 4, h = bh & 15;
    const int tq0 = blockIdx.x * 128;

    const float* Qb = g_Q + (size_t)b * TT * DM + h * DD;
    const float* Kb = g_K + (size_t)b * TT * DM + h * DD;

    if (tid < 128) Cs[tid] = 0.f;

    float csum[4][2];
    #pragma unroll
    for (int ni = 0; ni < 4; ni++) { csum[ni][0] = 0.f; csum[ni][1] = 0.f; }

    for (int tkc = 0; tkc < 16; tkc++) {
        __syncthreads();                      // protect Rs from prior readers
        if (tid < 128) Rs[tid] = g_R[bh * TT + tkc * 128 + tid];

        float c[4][4][4];
        #pragma unroll
        for (int mi = 0; mi < 4; mi++)
            #pragma unroll
            for (int ni = 0; ni < 4; ni++)
                #pragma unroll
                for (int r = 0; r < 4; r++) c[mi][ni][r] = 0.f;

        #pragma unroll
        for (int kh = 0; kh < 2; kh++) {
            __syncthreads();
            load_chunk_tf(Ks, Kb, tkc * 128, kh, tid);
            load_chunk_tf(Qs, Qb, tq0, kh, tid);
            __syncthreads();
            score_mma_chunk(c, Ks, Qs, wm, wn, grp, t4);
        }
        #pragma unroll
        for (int mi = 0; mi < 4; mi++) {
            float r0 = Rs[wm * 64 + mi * 16 + grp];
            float r1 = Rs[wm * 64 + mi * 16 + grp + 8];
            #pragma unroll
            for (int ni = 0; ni < 4; ni++) {
                csum[ni][0] += fast_exp(c[mi][ni][0] * 0.125f) * r0
                             + fast_exp(c[mi][ni][2] * 0.125f) * r1;
                csum[ni][1] += fast_exp(c[mi][ni][1] * 0.125f) * r0
                             + fast_exp(c[mi][ni][3] * 0.125f) * r1;
            }
        }
    }

    __syncthreads();
    #pragma unroll
    for (int ni = 0; ni < 4; ni++)
        #pragma unroll
        for (int p = 0; p < 2; p++) {
            float v = csum[ni][p];
            v += __shfl_xor_sync(0xffffffffu, v, 4);
            v += __shfl_xor_sync(0xffffffffu, v, 8);
            v += __shfl_xor_sync(0xffffffffu, v, 16);
            if (grp == 0) atomicAdd(&Cs[wn * 32 + ni * 8 + 2 * t4 + p], v);
        }
    __syncthreads();
    if (tid < 128) g_C[bh * TT + tq0 + tid] = Cs[tid];
}

// ---------------- launch -----------------------------------------------------
extern "C" void kernel_launch(void* const* d_in, const int* in_sizes, int n_in,
                              void* d_out, int out_size)
{
    const float* x  = (const float*)d_in[0];
    const float* Wq = (const float*)d_in[1];
    const float* bq = (const float*)d_in[2];
    const float* Wk = (const float*)d_in[3];
    const float* bk = (const float*)d_in[4];
    const float* Wv = (const float*)d_in[5];
    const float* bv = (const float*)d_in[6];
    const float* Wo = (const float*)d_in[7];
    const float* bo = (const float*)d_in[8];
    float* out = (float*)d_out;

    float *Qp, *Kp, *Vp, *Cp;
    cudaGetSymbolAddress((void**)&Qp, g_Q);
    cudaGetSymbolAddress((void**)&Kp, g_K);
    cudaGetSymbolAddress((void**)&Vp, g_V);
    cudaGetSymbolAddress((void**)&Cp, g_C);

    dim3 gproj(DM / 128, BT / 128);   // (8, 32)

    gemm_tf32<<<gproj, 256>>>(x, Wq, bq, nullptr, Qp, BT, DM, DM);
    gemm_tf32<<<gproj, 256>>>(x, Wk, bk, nullptr, Kp, BT, DM, DM);
    gemm_tf32<<<gproj, 256>>>(x, Wv, bv, nullptr, Vp, BT, DM, DM);
    attn_z_mma<<<dim3(TT / 128, BHD), 256>>>();
    attn_cs_mma<<<dim3(TT / 128, BHD), 256>>>();
    gemm_tf32<<<gproj, 256>>>(Vp, Wo, bo, Cp, out, BT, DM, DM);
}

// round 9
// speedup vs baseline: 2.0784x; 1.1227x over previous
#include <cuda_runtime.h>
#include <cstdint>

#define BB 2
#define TT 2048
#define HH 16
#define DD 64
#define DM 1024
#define BT (BB*TT)      // 4096
#define BHD (BB*HH)     // 32

// dynamic smem for attention kernels: Ks[64][132] + Qs[64][132] + 256 floats
#define ATTN_SMEM_WORDS (2 * 64 * 132 + 256)
#define ATTN_SMEM_BYTES (ATTN_SMEM_WORDS * 4)

// ---------------- static scratch ----------------
__device__ float g_Q[(size_t)BT*DM];   // 16 MB
__device__ float g_K[(size_t)BT*DM];   // 16 MB
__device__ float g_V[(size_t)BT*DM];   // 16 MB
__device__ float g_R[BHD*TT];          // 1/Z per (b,h,tk)
__device__ float g_C[BHD*TT];          // colsum per (b,h,tq)

// ---------------- helpers ----------------
__device__ __forceinline__ uint32_t f2tf(float x) {
    uint32_t r;
    asm("cvt.rna.tf32.f32 %0, %1;" : "=r"(r) : "f"(x));
    return r;
}

__device__ __forceinline__ float ex2f(float x) {
    float r;
    asm("ex2.approx.f32 %0, %1;" : "=f"(r) : "f"(x));
    return r;
}
// exp(s * 0.125) = 2^(s * 0.125*log2(e))
#define EXPS(s) ex2f((s) * 0.18033688011112042f)

__device__ __forceinline__ void mma8(float c[4],
    uint32_t a0, uint32_t a1, uint32_t a2, uint32_t a3,
    uint32_t b0, uint32_t b1)
{
    asm volatile(
        "mma.sync.aligned.m16n8k8.row.col.f32.tf32.tf32.f32 "
        "{%0,%1,%2,%3}, {%4,%5,%6,%7}, {%8,%9}, {%0,%1,%2,%3};"
        : "+f"(c[0]), "+f"(c[1]), "+f"(c[2]), "+f"(c[3])
        : "r"(a0), "r"(a1), "r"(a2), "r"(a3), "r"(b0), "r"(b1));
}

// ============ tf32 tensor GEMM: C = (A*scale) @ W + bias ===================
// A: [M,K] fp32 row-major, W: [K,N] fp32 row-major, bias: [N]
// scale (optional): per-(m, head(k)) multiplier: scale[((m/T)*H + k/D)*T + m%T]
// CTA 128x128, 8 warps (2m x 4n), warp tile 64x32, k-chunk 32.
// Register double-buffer: chunk kb+32 LDG'd during chunk kb MMA.
__global__ void __launch_bounds__(256) gemm_tf32(
    const float* __restrict__ A, const float* __restrict__ W,
    const float* __restrict__ bias, const float* __restrict__ scale,
    float* __restrict__ Cout, int M, int N, int K)
{
    __shared__ uint32_t As[32][132];   // [k][m]
    __shared__ uint32_t Bs[128][33];   // [n][k] (W transposed)

    const int tid = threadIdx.x, lane = tid & 31, wid = tid >> 5;
    const int grp = lane >> 2, t4 = lane & 3;
    const int wm = wid >> 2, wn = wid & 3;
    const int m0 = blockIdx.y * 128, n0 = blockIdx.x * 128;

    float c[4][4][4];
    #pragma unroll
    for (int mi = 0; mi < 4; mi++)
        #pragma unroll
        for (int ni = 0; ni < 4; ni++)
            #pragma unroll
            for (int r = 0; r < 4; r++) c[mi][ni][r] = 0.f;

    const int am = tid >> 1;            // A row within tile (0..127)
    const int ak = (tid & 1) * 16;      // A col base (0 or 16)
    const int bk = tid >> 3;            // W row (k, 0..31)
    const int bn = (tid & 7) * 4;       // W col base, +32*i

    float4 aR[4], wR[4];
    float sc = 1.f;
    // prologue: load chunk 0
    #pragma unroll
    for (int i = 0; i < 4; i++)
        aR[i] = *(const float4*)&A[(size_t)(m0 + am) * K + ak + i * 4];
    #pragma unroll
    for (int i = 0; i < 4; i++)
        wR[i] = *(const float4*)&W[(size_t)bk * N + n0 + bn + i * 32];
    if (scale) {
        int mg = m0 + am;
        sc = scale[(((mg / TT) * HH) + (0 / DD)) * TT + (mg % TT)];
    }

    for (int kb = 0; kb < K; kb += 32) {
        // store current chunk to smem (tf32 bits, A scaled)
        #pragma unroll
        for (int i = 0; i < 4; i++) {
            float4 v = aR[i];
            if (scale) { v.x *= sc; v.y *= sc; v.z *= sc; v.w *= sc; }
            As[ak + i * 4 + 0][am] = f2tf(v.x);
            As[ak + i * 4 + 1][am] = f2tf(v.y);
            As[ak + i * 4 + 2][am] = f2tf(v.z);
            As[ak + i * 4 + 3][am] = f2tf(v.w);
        }
        #pragma unroll
        for (int i = 0; i < 4; i++) {
            Bs[bn + i * 32 + 0][bk] = f2tf(wR[i].x);
            Bs[bn + i * 32 + 1][bk] = f2tf(wR[i].y);
            Bs[bn + i * 32 + 2][bk] = f2tf(wR[i].z);
            Bs[bn + i * 32 + 3][bk] = f2tf(wR[i].w);
        }
        __syncthreads();

        // prefetch next chunk (overlaps the MMA below)
        if (kb + 32 < K) {
            #pragma unroll
            for (int i = 0; i < 4; i++)
                aR[i] = *(const float4*)&A[(size_t)(m0 + am) * K + kb + 32 + ak + i * 4];
            #pragma unroll
            for (int i = 0; i < 4; i++)
                wR[i] = *(const float4*)&W[(size_t)(kb + 32 + bk) * N + n0 + bn + i * 32];
            if (scale) {
                int mg = m0 + am;
                sc = scale[(((mg / TT) * HH) + ((kb + 32) / DD)) * TT + (mg % TT)];
            }
        }

        #pragma unroll
        for (int ks = 0; ks < 4; ks++) {
            const int k0 = ks * 8;
            uint32_t a[4][4], b[4][2];
            #pragma unroll
            for (int mi = 0; mi < 4; mi++) {
                int m = wm * 64 + mi * 16 + grp;
                a[mi][0] = As[k0 + t4][m];
                a[mi][1] = As[k0 + t4][m + 8];
                a[mi][2] = As[k0 + t4 + 4][m];
                a[mi][3] = As[k0 + t4 + 4][m + 8];
            }
            #pragma unroll
            for (int ni = 0; ni < 4; ni++) {
                int n = wn * 32 + ni * 8 + grp;
                b[ni][0] = Bs[n][k0 + t4];
                b[ni][1] = Bs[n][k0 + t4 + 4];
            }
            #pragma unroll
            for (int mi = 0; mi < 4; mi++)
                #pragma unroll
                for (int ni = 0; ni < 4; ni++)
                    mma8(c[mi][ni], a[mi][0], a[mi][1], a[mi][2], a[mi][3],
                         b[ni][0], b[ni][1]);
        }
        __syncthreads();
    }

    #pragma unroll
    for (int mi = 0; mi < 4; mi++) {
        int r0 = m0 + wm * 64 + mi * 16 + grp;
        #pragma unroll
        for (int ni = 0; ni < 4; ni++) {
            int cb = n0 + wn * 32 + ni * 8 + 2 * t4;
            float b0 = bias[cb], b1 = bias[cb + 1];
            float2 v0 = make_float2(c[mi][ni][0] + b0, c[mi][ni][1] + b1);
            float2 v1 = make_float2(c[mi][ni][2] + b0, c[mi][ni][3] + b1);
            *(float2*)&Cout[(size_t)r0 * N + cb]       = v0;
            *(float2*)&Cout[(size_t)(r0 + 8) * N + cb] = v1;
        }
    }
}

// ---- 128-row x 64-d tile helpers (8 float4 per thread, 256 threads) -------
__device__ __forceinline__ void tile64_ldg(
    float4 reg[8], const float* __restrict__ src, int row0, int tid)
{
    #pragma unroll
    for (int j = 0; j < 8; j++) {
        int pos = j * 256 + tid;        // 0..2047
        int row = pos >> 4;             // 0..127
        int d4  = (pos & 15) * 4;       // 0..60
        reg[j] = *(const float4*)&src[(size_t)(row0 + row) * DM + d4];
    }
}

__device__ __forceinline__ void tile64_sts(
    uint32_t dst[64][132], const float4 reg[8], int tid)
{
    #pragma unroll
    for (int j = 0; j < 8; j++) {
        int pos = j * 256 + tid;
        int row = pos >> 4;
        int d4  = (pos & 15) * 4;
        dst[d4 + 0][row] = f2tf(reg[j].x);
        dst[d4 + 1][row] = f2tf(reg[j].y);
        dst[d4 + 2][row] = f2tf(reg[j].z);
        dst[d4 + 3][row] = f2tf(reg[j].w);
    }
}

// ---- full-depth (k=64) score MMA: c += Ks[128 m] x Qs[128 n] --------------
__device__ __forceinline__ void score_mma64(
    float c[4][4][4], const uint32_t Ks[64][132], const uint32_t Qs[64][132],
    int wm, int wn, int grp, int t4)
{
    #pragma unroll
    for (int ks = 0; ks < 8; ks++) {
        const int k0 = ks * 8;
        uint32_t a[4][4], b[4][2];
        #pragma unroll
        for (int mi = 0; mi < 4; mi++) {
            int m = wm * 64 + mi * 16 + grp;
            a[mi][0] = Ks[k0 + t4][m];
            a[mi][1] = Ks[k0 + t4][m + 8];
            a[mi][2] = Ks[k0 + t4 + 4][m];
            a[mi][3] = Ks[k0 + t4 + 4][m + 8];
        }
        #pragma unroll
        for (int ni = 0; ni < 4; ni++) {
            int n = wn * 32 + ni * 8 + grp;
            b[ni][0] = Qs[k0 + t4][n];
            b[ni][1] = Qs[k0 + t4 + 4][n];
        }
        #pragma unroll
        for (int mi = 0; mi < 4; mi++)
            #pragma unroll
            for (int ni = 0; ni < 4; ni++)
                mma8(c[mi][ni], a[mi][0], a[mi][1], a[mi][2], a[mi][3],
                     b[ni][0], b[ni][1]);
    }
}

// ============ pass 1: Z[tk] = sum_tq exp(s/8); R = 1/Z =====================
// K tile resident; Q tiles streamed with register double-buffering.
__global__ void __launch_bounds__(256) attn_z_mma()
{
    extern __shared__ uint32_t smem[];
    uint32_t (*Ks)[132] = (uint32_t(*)[132])smem;
    uint32_t (*Qs)[132] = (uint32_t(*)[132])(smem + 64 * 132);
    float* Zs = (float*)(smem + 2 * 64 * 132);

    const int tid = threadIdx.x, lane = tid & 31, wid = tid >> 5;
    const int grp = lane >> 2, t4 = lane & 3;
    const int wm = wid >> 2, wn = wid & 3;
    const int bh = blockIdx.y, b = bh >> 4, h = bh & 15;
    const int tk0 = blockIdx.x * 128;

    const float* Qb = g_Q + (size_t)b * TT * DM + h * DD;
    const float* Kb = g_K + (size_t)b * TT * DM + h * DD;

    if (tid < 128) Zs[tid] = 0.f;

    // K tile resident for whole CTA
    {
        float4 kreg[8];
        tile64_ldg(kreg, Kb, tk0, tid);
        tile64_sts(Ks, kreg, tid);
    }
    // prologue Q[0]
    float4 qreg[8];
    tile64_ldg(qreg, Qb, 0, tid);

    float zacc[4][2];
    #pragma unroll
    for (int mi = 0; mi < 4; mi++) { zacc[mi][0] = 0.f; zacc[mi][1] = 0.f; }

    for (int tqc = 0; tqc < 16; tqc++) {
        tile64_sts(Qs, qreg, tid);
        __syncthreads();                       // Ks (first iter) + Qs ready
        if (tqc < 15) tile64_ldg(qreg, Qb, (tqc + 1) * 128, tid);

        float c[4][4][4];
        #pragma unroll
        for (int mi = 0; mi < 4; mi++)
            #pragma unroll
            for (int ni = 0; ni < 4; ni++)
                #pragma unroll
                for (int r = 0; r < 4; r++) c[mi][ni][r] = 0.f;

        score_mma64(c, Ks, Qs, wm, wn, grp, t4);

        #pragma unroll
        for (int mi = 0; mi < 4; mi++)
            #pragma unroll
            for (int ni = 0; ni < 4; ni++) {
                zacc[mi][0] += EXPS(c[mi][ni][0]) + EXPS(c[mi][ni][1]);
                zacc[mi][1] += EXPS(c[mi][ni][2]) + EXPS(c[mi][ni][3]);
            }
        __syncthreads();                       // all reads of Qs done
    }

    #pragma unroll
    for (int mi = 0; mi < 4; mi++)
        #pragma unroll
        for (int hf = 0; hf < 2; hf++) {
            float v = zacc[mi][hf];
            v += __shfl_xor_sync(0xffffffffu, v, 1);
            v += __shfl_xor_sync(0xffffffffu, v, 2);
            if (t4 == 0) atomicAdd(&Zs[wm * 64 + mi * 16 + grp + hf * 8], v);
        }
    __syncthreads();
    if (tid < 128) g_R[bh * TT + tk0 + tid] = 1.0f / Zs[tid];
}

// ============ pass 2: colsum[tq] = sum_tk exp(s/8) * R[tk] =================
// Q tile resident; K tiles streamed with register double-buffering.
__global__ void __launch_bounds__(256) attn_cs_mma()
{
    extern __shared__ uint32_t smem[];
    uint32_t (*Ks)[132] = (uint32_t(*)[132])smem;
    uint32_t (*Qs)[132] = (uint32_t(*)[132])(smem + 64 * 132);
    float* Rs = (float*)(smem + 2 * 64 * 132);
    float* Cs = (float*)(smem + 2 * 64 * 132 + 128);

    const int tid = threadIdx.x, lane = tid & 31, wid = tid >> 5;
    const int grp = lane >> 2, t4 = lane & 3;
    const int wm = wid >> 2, wn = wid & 3;
    const int bh = blockIdx.y, b = bh >> 4, h = bh & 15;
    const int tq0 = blockIdx.x * 128;

    const float* Qb = g_Q + (size_t)b * TT * DM + h * DD;
    const float* Kb = g_K + (size_t)b * TT * DM + h * DD;

    if (tid < 128) Cs[tid] = 0.f;

    // Q tile resident
    {
        float4 qreg[8];
        tile64_ldg(qreg, Qb, tq0, tid);
        tile64_sts(Qs, qreg, tid);
    }
    // prologue K[0]
    float4 kreg[8];
    tile64_ldg(kreg, Kb, 0, tid);

    float csum[4][2];
    #pragma unroll
    for (int ni = 0; ni < 4; ni++) { csum[ni][0] = 0.f; csum[ni][1] = 0.f; }

    for (int tkc = 0; tkc < 16; tkc++) {
        tile64_sts(Ks, kreg, tid);
        if (tid < 128) Rs[tid] = g_R[bh * TT + tkc * 128 + tid];
        __syncthreads();                       // Qs (first iter) + Ks + Rs ready
        if (tkc < 15) tile64_ldg(kreg, Kb, (tkc + 1) * 128, tid);

        float c[4][4][4];
        #pragma unroll
        for (int mi = 0; mi < 4; mi++)
            #pragma unroll
            for (int ni = 0; ni < 4; ni++)
                #pragma unroll
                for (int r = 0; r < 4; r++) c[mi][ni][r] = 0.f;

        score_mma64(c, Ks, Qs, wm, wn, grp, t4);

        #pragma unroll
        for (int mi = 0; mi < 4; mi++) {
            float r0 = Rs[wm * 64 + mi * 16 + grp];
            float r1 = Rs[wm * 64 + mi * 16 + grp + 8];
            #pragma unroll
            for (int ni = 0; ni < 4; ni++) {
                csum[ni][0] += EXPS(c[mi][ni][0]) * r0 + EXPS(c[mi][ni][2]) * r1;
                csum[ni][1] += EXPS(c[mi][ni][1]) * r0 + EXPS(c[mi][ni][3]) * r1;
            }
        }
        __syncthreads();                       // all reads of Ks/Rs done
    }

    #pragma unroll
    for (int ni = 0; ni < 4; ni++)
        #pragma unroll
        for (int p = 0; p < 2; p++) {
            float v = csum[ni][p];
            v += __shfl_xor_sync(0xffffffffu, v, 4);
            v += __shfl_xor_sync(0xffffffffu, v, 8);
            v += __shfl_xor_sync(0xffffffffu, v, 16);
            if (grp == 0) atomicAdd(&Cs[wn * 32 + ni * 8 + 2 * t4 + p], v);
        }
    __syncthreads();
    if (tid < 128) g_C[bh * TT + tq0 + tid] = Cs[tid];
}

// ---------------- launch -----------------------------------------------------
extern "C" void kernel_launch(void* const* d_in, const int* in_sizes, int n_in,
                              void* d_out, int out_size)
{
    const float* x  = (const float*)d_in[0];
    const float* Wq = (const float*)d_in[1];
    const float* bq = (const float*)d_in[2];
    const float* Wk = (const float*)d_in[3];
    const float* bk = (const float*)d_in[4];
    const float* Wv = (const float*)d_in[5];
    const float* bv = (const float*)d_in[6];
    const float* Wo = (const float*)d_in[7];
    const float* bo = (const float*)d_in[8];
    float* out = (float*)d_out;

    float *Qp, *Kp, *Vp, *Cp;
    cudaGetSymbolAddress((void**)&Qp, g_Q);
    cudaGetSymbolAddress((void**)&Kp, g_K);
    cudaGetSymbolAddress((void**)&Vp, g_V);
    cudaGetSymbolAddress((void**)&Cp, g_C);

    static bool attr_done = false;
    if (!attr_done) {
        cudaFuncSetAttribute(attn_z_mma,
            cudaFuncAttributeMaxDynamicSharedMemorySize, ATTN_SMEM_BYTES);
        cudaFuncSetAttribute(attn_cs_mma,
            cudaFuncAttributeMaxDynamicSharedMemorySize, ATTN_SMEM_BYTES);
        attr_done = true;
    }

    dim3 gproj(DM / 128, BT / 128);   // (8, 32)

    gemm_tf32<<<gproj, 256>>>(x, Wq, bq, nullptr, Qp, BT, DM, DM);
    gemm_tf32<<<gproj, 256>>>(x, Wk, bk, nullptr, Kp, BT, DM, DM);
    gemm_tf32<<<gproj, 256>>>(x, Wv, bv, nullptr, Vp, BT, DM, DM);
    attn_z_mma<<<dim3(TT / 128, BHD), 256, ATTN_SMEM_BYTES>>>();
    attn_cs_mma<<<dim3(TT / 128, BHD), 256, ATTN_SMEM_BYTES>>>();
    gemm_tf32<<<gproj, 256>>>(Vp, Wo, bo, Cp, out, BT, DM, DM);
}

// round 10
// speedup vs baseline: 3.5782x; 1.7216x over previous
#include <cuda_runtime.h>
#include <cstdint>

#define BB 2
#define TT 2048
#define HH 16
#define DD 64
#define DM 1024
#define BT (BB*TT)      // 4096
#define BHD (BB*HH)     // 32

// ---------------- static scratch ----------------
__device__ float g_Q[(size_t)BT*DM];   // 16 MB (tf32-rounded bits)
__device__ float g_K[(size_t)BT*DM];   // 16 MB (tf32-rounded bits)
__device__ float g_V[(size_t)BT*DM];   // 16 MB
__device__ float g_R[BHD*TT];          // 1/Z per (b,h,tk)
__device__ float g_C[BHD*TT];          // colsum per (b,h,tq)

// ---------------- low-level helpers ----------------
__device__ __forceinline__ uint32_t f2tf(float x) {
    uint32_t r;
    asm("cvt.rna.tf32.f32 %0, %1;" : "=r"(r) : "f"(x));
    return r;
}

__device__ __forceinline__ float ex2f(float x) {
    float r;
    asm("ex2.approx.f32 %0, %1;" : "=f"(r) : "f"(x));
    return r;
}
// exp(s * 0.125) = 2^(s * 0.125*log2(e))
#define EXPS(s) ex2f((s) * 0.18033688011112042f)

__device__ __forceinline__ void mma8(float c[4],
    uint32_t a0, uint32_t a1, uint32_t a2, uint32_t a3,
    uint32_t b0, uint32_t b1)
{
    asm volatile(
        "mma.sync.aligned.m16n8k8.row.col.f32.tf32.tf32.f32 "
        "{%0,%1,%2,%3}, {%4,%5,%6,%7}, {%8,%9}, {%0,%1,%2,%3};"
        : "+f"(c[0]), "+f"(c[1]), "+f"(c[2]), "+f"(c[3])
        : "r"(a0), "r"(a1), "r"(a2), "r"(a3), "r"(b0), "r"(b1));
}

__device__ __forceinline__ void cp16(uint32_t smem_b, const void* g) {
    asm volatile("cp.async.ca.shared.global [%0], [%1], 16;"
                 :: "r"(smem_b), "l"(g));
}
#define CP_COMMIT() asm volatile("cp.async.commit_group;")
#define CP_WAIT1()  asm volatile("cp.async.wait_group 1;")

// ================= gemm with cp.async double-buffered k-chunks ==============
// C = A @ W + bias; A:[M,K] fp32 row-major, W:[K,N] fp32 row-major.
// In-loop RNA tf32 rounding of both operands. Optional tf32 rounding of output.
// CTA 128x128, 8 warps (2m x 4n), k-chunk 32.
#define GA_STR 36                       // A smem row stride (words), 36%32=4
#define GB_STR 136                      // B smem row stride (words), 136%32=8
#define G_BUFA (128*GA_STR)             // 4608 words
#define G_BUFB (32*GB_STR)              // 4352 words
#define G_BUF  (G_BUFA + G_BUFB)        // 8960 words per buffer
#define GEMM_SMEM_BYTES (2*G_BUF*4)     // 71680 B

__device__ __forceinline__ void gemm_issue_chunk(
    uint32_t sb, int buf, const float* __restrict__ A,
    const float* __restrict__ W, int m0, int n0, int kb, int K, int N, int tid)
{
    uint32_t base = sb + (uint32_t)buf * G_BUF * 4;
    #pragma unroll
    for (int j = 0; j < 4; j++) {           // A: 128x32 floats
        int pos = j * 256 + tid;
        int row = pos >> 3, c4 = (pos & 7) * 4;
        cp16(base + (row * GA_STR + c4) * 4,
             A + (size_t)(m0 + row) * K + kb + c4);
    }
    #pragma unroll
    for (int j = 0; j < 4; j++) {           // B: 32x128 floats
        int pos = j * 256 + tid;
        int row = pos >> 5, n4 = (pos & 31) * 4;
        cp16(base + (G_BUFA + row * GB_STR + n4) * 4,
             W + (size_t)(kb + row) * N + n0 + n4);
    }
}

__global__ void __launch_bounds__(256, 2) gemm_cp(
    const float* __restrict__ A, const float* __restrict__ W,
    const float* __restrict__ bias, float* __restrict__ Cout,
    int M, int N, int K, int round_out)
{
    extern __shared__ uint32_t smem[];
    uint32_t sb = (uint32_t)__cvta_generic_to_shared(smem);

    const int tid = threadIdx.x, lane = tid & 31, wid = tid >> 5;
    const int grp = lane >> 2, t4 = lane & 3;
    const int wm = wid >> 2, wn = wid & 3;
    const int m0 = blockIdx.y * 128, n0 = blockIdx.x * 128;

    float c[4][4][4];
    #pragma unroll
    for (int mi = 0; mi < 4; mi++)
        #pragma unroll
        for (int ni = 0; ni < 4; ni++)
            #pragma unroll
            for (int r = 0; r < 4; r++) c[mi][ni][r] = 0.f;

    const int nchunks = K / 32;   // 32
    gemm_issue_chunk(sb, 0, A, W, m0, n0, 0, K, N, tid);
    CP_COMMIT();
    gemm_issue_chunk(sb, 1, A, W, m0, n0, 32, K, N, tid);
    CP_COMMIT();

    for (int ci = 0; ci < nchunks; ci++) {
        const int buf = ci & 1;
        const uint32_t* As = smem + buf * G_BUF;
        const uint32_t* Bs = As + G_BUFA;
        CP_WAIT1();
        __syncthreads();

        #pragma unroll
        for (int ks = 0; ks < 4; ks++) {
            const int k0 = ks * 8;
            uint32_t a[4][4], b[4][2];
            #pragma unroll
            for (int mi = 0; mi < 4; mi++) {
                int m = wm * 64 + mi * 16 + grp;
                a[mi][0] = f2tf(__uint_as_float(As[m * GA_STR + k0 + t4]));
                a[mi][1] = f2tf(__uint_as_float(As[(m + 8) * GA_STR + k0 + t4]));
                a[mi][2] = f2tf(__uint_as_float(As[m * GA_STR + k0 + t4 + 4]));
                a[mi][3] = f2tf(__uint_as_float(As[(m + 8) * GA_STR + k0 + t4 + 4]));
            }
            #pragma unroll
            for (int ni = 0; ni < 4; ni++) {
                int n = wn * 32 + ni * 8 + grp;
                b[ni][0] = f2tf(__uint_as_float(Bs[(k0 + t4) * GB_STR + n]));
                b[ni][1] = f2tf(__uint_as_float(Bs[(k0 + t4 + 4) * GB_STR + n]));
            }
            #pragma unroll
            for (int mi = 0; mi < 4; mi++)
                #pragma unroll
                for (int ni = 0; ni < 4; ni++)
                    mma8(c[mi][ni], a[mi][0], a[mi][1], a[mi][2], a[mi][3],
                         b[ni][0], b[ni][1]);
        }
        __syncthreads();
        if (ci + 2 < nchunks)
            gemm_issue_chunk(sb, buf, A, W, m0, n0, (ci + 2) * 32, K, N, tid);
        CP_COMMIT();
    }

    #pragma unroll
    for (int mi = 0; mi < 4; mi++) {
        int r0 = m0 + wm * 64 + mi * 16 + grp;
        #pragma unroll
        for (int ni = 0; ni < 4; ni++) {
            int cb = n0 + wn * 32 + ni * 8 + 2 * t4;
            float b0 = bias[cb], b1 = bias[cb + 1];
            float v00 = c[mi][ni][0] + b0, v01 = c[mi][ni][1] + b1;
            float v10 = c[mi][ni][2] + b0, v11 = c[mi][ni][3] + b1;
            if (round_out) {
                v00 = __uint_as_float(f2tf(v00)); v01 = __uint_as_float(f2tf(v01));
                v10 = __uint_as_float(f2tf(v10)); v11 = __uint_as_float(f2tf(v11));
            }
            *(float2*)&Cout[(size_t)r0 * N + cb]       = make_float2(v00, v01);
            *(float2*)&Cout[(size_t)(r0 + 8) * N + cb] = make_float2(v10, v11);
        }
    }
}

// ================= attention kernels =======================================
#define A_STR  68                       // tile row stride (words), 68%32=4
#define A_TILE (128*A_STR)              // 8704 words per 128x64 tile
#define ATTN_SMEM_BYTES ((3*A_TILE + 256)*4)   // 105472 B

__device__ __forceinline__ void attn_issue_tile(
    uint32_t sb, uint32_t off_words, const float* __restrict__ src,
    int row0, int tid)
{
    #pragma unroll
    for (int j = 0; j < 8; j++) {           // 128x64 floats = 2048 x 16B
        int pos = j * 256 + tid;
        int row = pos >> 4, d4 = (pos & 15) * 4;
        cp16(sb + (off_words + row * A_STR + d4) * 4,
             src + (size_t)(row0 + row) * DM + d4);
    }
}

// c[128 a-rows][128 b-rows] += Atile . Btile^T over k=64 (raw tf32 bits)
__device__ __forceinline__ void score_mma64(
    float c[4][4][4], const uint32_t* __restrict__ Ka,
    const uint32_t* __restrict__ Qb, int wm, int wn, int grp, int t4)
{
    #pragma unroll
    for (int ks = 0; ks < 8; ks++) {
        const int k0 = ks * 8;
        uint32_t a[4][4], b[4][2];
        #pragma unroll
        for (int mi = 0; mi < 4; mi++) {
            int m = wm * 64 + mi * 16 + grp;
            a[mi][0] = Ka[m * A_STR + k0 + t4];
            a[mi][1] = Ka[(m + 8) * A_STR + k0 + t4];
            a[mi][2] = Ka[m * A_STR + k0 + t4 + 4];
            a[mi][3] = Ka[(m + 8) * A_STR + k0 + t4 + 4];
        }
        #pragma unroll
        for (int ni = 0; ni < 4; ni++) {
            int n = wn * 32 + ni * 8 + grp;
            b[ni][0] = Qb[n * A_STR + k0 + t4];
            b[ni][1] = Qb[n * A_STR + k0 + t4 + 4];
        }
        #pragma unroll
        for (int mi = 0; mi < 4; mi++)
            #pragma unroll
            for (int ni = 0; ni < 4; ni++)
                mma8(c[mi][ni], a[mi][0], a[mi][1], a[mi][2], a[mi][3],
                     b[ni][0], b[ni][1]);
    }
}

// ---- pass 1: Z[tk] = sum_tq exp(s/8); R = 1/Z. K resident, Q streamed. ----
__global__ void __launch_bounds__(256, 2) attn_z_mma()
{
    extern __shared__ uint32_t smem[];
    uint32_t sb = (uint32_t)__cvta_generic_to_shared(smem);
    const uint32_t* Ks = smem;
    float* Zs = (float*)(smem + 3 * A_TILE);

    const int tid = threadIdx.x, lane = tid & 31, wid = tid >> 5;
    const int grp = lane >> 2, t4 = lane & 3;
    const int wm = wid >> 2, wn = wid & 3;
    const int bh = blockIdx.y, b = bh >> 4, h = bh & 15;
    const int tk0 = blockIdx.x * 128;

    const float* Qb = g_Q + (size_t)b * TT * DM + h * DD;
    const float* Kb = g_K + (size_t)b * TT * DM + h * DD;

    if (tid < 128) Zs[tid] = 0.f;

    // group0: K tile + Q0; group1: Q1
    attn_issue_tile(sb, 0, Kb, tk0, tid);
    attn_issue_tile(sb, A_TILE, Qb, 0, tid);
    CP_COMMIT();
    attn_issue_tile(sb, 2 * A_TILE, Qb, 128, tid);
    CP_COMMIT();

    float zacc[4][2];
    #pragma unroll
    for (int mi = 0; mi < 4; mi++) { zacc[mi][0] = 0.f; zacc[mi][1] = 0.f; }

    for (int tqc = 0; tqc < 16; tqc++) {
        const int buf = tqc & 1;
        const uint32_t* Qs = smem + (1 + buf) * A_TILE;
        CP_WAIT1();
        __syncthreads();

        float c[4][4][4];
        #pragma unroll
        for (int mi = 0; mi < 4; mi++)
            #pragma unroll
            for (int ni = 0; ni < 4; ni++)
                #pragma unroll
                for (int r = 0; r < 4; r++) c[mi][ni][r] = 0.f;

        score_mma64(c, Ks, Qs, wm, wn, grp, t4);

        #pragma unroll
        for (int mi = 0; mi < 4; mi++)
            #pragma unroll
            for (int ni = 0; ni < 4; ni++) {
                zacc[mi][0] += EXPS(c[mi][ni][0]) + EXPS(c[mi][ni][1]);
                zacc[mi][1] += EXPS(c[mi][ni][2]) + EXPS(c[mi][ni][3]);
            }
        __syncthreads();
        if (tqc + 2 < 16)
            attn_issue_tile(sb, (1 + buf) * A_TILE, Qb, (tqc + 2) * 128, tid);
        CP_COMMIT();
    }

    #pragma unroll
    for (int mi = 0; mi < 4; mi++)
        #pragma unroll
        for (int hf = 0; hf < 2; hf++) {
            float v = zacc[mi][hf];
            v += __shfl_xor_sync(0xffffffffu, v, 1);
            v += __shfl_xor_sync(0xffffffffu, v, 2);
            if (t4 == 0) atomicAdd(&Zs[wm * 64 + mi * 16 + grp + hf * 8], v);
        }
    __syncthreads();
    if (tid < 128) g_R[bh * TT + tk0 + tid] = 1.0f / Zs[tid];
}

// ---- pass 2: colsum[tq] = sum_tk exp(s/8)*R[tk]. Q resident, K streamed. --
__global__ void __launch_bounds__(256, 2) attn_cs_mma()
{
    extern __shared__ uint32_t smem[];
    uint32_t sb = (uint32_t)__cvta_generic_to_shared(smem);
    const uint32_t* Qs = smem;
    float* Rs = (float*)(smem + 3 * A_TILE);
    float* Cs = Rs + 128;

    const int tid = threadIdx.x, lane = tid & 31, wid = tid >> 5;
    const int grp = lane >> 2, t4 = lane & 3;
    const int wm = wid >> 2, wn = wid & 3;
    const int bh = blockIdx.y, b = bh >> 4, h = bh & 15;
    const int tq0 = blockIdx.x * 128;

    const float* Qb = g_Q + (size_t)b * TT * DM + h * DD;
    const float* Kb = g_K + (size_t)b * TT * DM + h * DD;

    if (tid < 128) Cs[tid] = 0.f;

    attn_issue_tile(sb, 0, Qb, tq0, tid);
    attn_issue_tile(sb, A_TILE, Kb, 0, tid);
    CP_COMMIT();
    attn_issue_tile(sb, 2 * A_TILE, Kb, 128, tid);
    CP_COMMIT();

    float csum[4][2];
    #pragma unroll
    for (int ni = 0; ni < 4; ni++) { csum[ni][0] = 0.f; csum[ni][1] = 0.f; }

    for (int tkc = 0; tkc < 16; tkc++) {
        const int buf = tkc & 1;
        const uint32_t* Ks = smem + (1 + buf) * A_TILE;
        CP_WAIT1();
        if (tid < 128) Rs[tid] = g_R[bh * TT + tkc * 128 + tid];
        __syncthreads();

        float c[4][4][4];
        #pragma unroll
        for (int mi = 0; mi < 4; mi++)
            #pragma unroll
            for (int ni = 0; ni < 4; ni++)
                #pragma unroll
                for (int r = 0; r < 4; r++) c[mi][ni][r] = 0.f;

        score_mma64(c, Ks, Qs, wm, wn, grp, t4);

        #pragma unroll
        for (int mi = 0; mi < 4; mi++) {
            float r0 = Rs[wm * 64 + mi * 16 + grp];
            float r1 = Rs[wm * 64 + mi * 16 + grp + 8];
            #pragma unroll
            for (int ni = 0; ni < 4; ni++) {
                csum[ni][0] += EXPS(c[mi][ni][0]) * r0 + EXPS(c[mi][ni][2]) * r1;
                csum[ni][1] += EXPS(c[mi][ni][1]) * r0 + EXPS(c[mi][ni][3]) * r1;
            }
        }
        __syncthreads();
        if (tkc + 2 < 16)
            attn_issue_tile(sb, (1 + buf) * A_TILE, Kb, (tkc + 2) * 128, tid);
        CP_COMMIT();
    }

    #pragma unroll
    for (int ni = 0; ni < 4; ni++)
        #pragma unroll
        for (int p = 0; p < 2; p++) {
            float v = csum[ni][p];
            v += __shfl_xor_sync(0xffffffffu, v, 4);
            v += __shfl_xor_sync(0xffffffffu, v, 8);
            v += __shfl_xor_sync(0xffffffffu, v, 16);
            if (grp == 0) atomicAdd(&Cs[wn * 32 + ni * 8 + 2 * t4 + p], v);
        }
    __syncthreads();
    if (tid < 128) g_C[bh * TT + tq0 + tid] = Cs[tid];
}

// ---- scale V rows by colsum and tf32-round, in place ----------------------
__global__ void __launch_bounds__(256) vscale()
{
    int t = blockIdx.x * 256 + threadIdx.x;
    int i = t * 4;                        // 4 floats per thread
    int m = i >> 10;                      // 0..4095
    int k = i & 1023;
    int head = k >> 6;
    float s = g_C[(((m >> 11) * HH) + head) * TT + (m & 2047)];
    float4 v = *(float4*)&g_V[i];
    v.x = __uint_as_float(f2tf(v.x * s));
    v.y = __uint_as_float(f2tf(v.y * s));
    v.z = __uint_as_float(f2tf(v.z * s));
    v.w = __uint_as_float(f2tf(v.w * s));
    *(float4*)&g_V[i] = v;
}

// ---------------- launch -----------------------------------------------------
extern "C" void kernel_launch(void* const* d_in, const int* in_sizes, int n_in,
                              void* d_out, int out_size)
{
    const float* x  = (const float*)d_in[0];
    const float* Wq = (const float*)d_in[1];
    const float* bq = (const float*)d_in[2];
    const float* Wk = (const float*)d_in[3];
    const float* bk = (const float*)d_in[4];
    const float* Wv = (const float*)d_in[5];
    const float* bv = (const float*)d_in[6];
    const float* Wo = (const float*)d_in[7];
    const float* bo = (const float*)d_in[8];
    float* out = (float*)d_out;

    float *Qp, *Kp, *Vp;
    cudaGetSymbolAddress((void**)&Qp, g_Q);
    cudaGetSymbolAddress((void**)&Kp, g_K);
    cudaGetSymbolAddress((void**)&Vp, g_V);

    cudaFuncSetAttribute(gemm_cp,
        cudaFuncAttributeMaxDynamicSharedMemorySize, GEMM_SMEM_BYTES);
    cudaFuncSetAttribute(attn_z_mma,
        cudaFuncAttributeMaxDynamicSharedMemorySize, ATTN_SMEM_BYTES);
    cudaFuncSetAttribute(attn_cs_mma,
        cudaFuncAttributeMaxDynamicSharedMemorySize, ATTN_SMEM_BYTES);

    dim3 gproj(DM / 128, BT / 128);   // (8, 32)

    gemm_cp<<<gproj, 256, GEMM_SMEM_BYTES>>>(x, Wq, bq, Qp, BT, DM, DM, 1);
    gemm_cp<<<gproj, 256, GEMM_SMEM_BYTES>>>(x, Wk, bk, Kp, BT, DM, DM, 1);
    gemm_cp<<<gproj, 256, GEMM_SMEM_BYTES>>>(x, Wv, bv, Vp, BT, DM, DM, 0);
    attn_z_mma<<<dim3(TT / 128, BHD), 256, ATTN_SMEM_BYTES>>>();
    attn_cs_mma<<<dim3(TT / 128, BHD), 256, ATTN_SMEM_BYTES>>>();
    vscale<<<(BT * DM) / 1024, 256>>>();
    gemm_cp<<<gproj, 256, GEMM_SMEM_BYTES>>>(Vp, Wo, bo, out, BT, DM, DM, 0);
}

// round 11
// speedup vs baseline: 3.6010x; 1.0064x over previous
#include <cuda_runtime.h>
#include <cuda_fp16.h>
#include <cstdint>

#define BB 2
#define TT 2048
#define HH 16
#define DD 64
#define DM 1024
#define BT (BB*TT)      // 4096
#define BHD (BB*HH)     // 32

// ---------------- static scratch ----------------
__device__ float g_X[(size_t)BT*DM];   // 16 MB (tf32-rounded x)
__device__ float g_Q[(size_t)BT*DM];   // 16 MB (tf32-rounded bits)
__device__ float g_K[(size_t)BT*DM];   // 16 MB (tf32-rounded bits)
__device__ float g_V[(size_t)BT*DM];   // 16 MB
__device__ __half g_E[(size_t)BHD*TT*TT];  // 268 MB exp(s/8) cache
__device__ float g_R[BHD*TT];          // 1/Z per (b,h,tk)

// ---------------- low-level helpers ----------------
__device__ __forceinline__ uint32_t f2tf(float x) {
    uint32_t r;
    asm("cvt.rna.tf32.f32 %0, %1;" : "=r"(r) : "f"(x));
    return r;
}

__device__ __forceinline__ float ex2f(float x) {
    float r;
    asm("ex2.approx.f32 %0, %1;" : "=f"(r) : "f"(x));
    return r;
}
// exp(s * 0.125) = 2^(s * 0.125*log2(e))
#define EXPS(s) ex2f((s) * 0.18033688011112042f)

__device__ __forceinline__ void mma8(float c[4],
    uint32_t a0, uint32_t a1, uint32_t a2, uint32_t a3,
    uint32_t b0, uint32_t b1)
{
    asm volatile(
        "mma.sync.aligned.m16n8k8.row.col.f32.tf32.tf32.f32 "
        "{%0,%1,%2,%3}, {%4,%5,%6,%7}, {%8,%9}, {%0,%1,%2,%3};"
        : "+f"(c[0]), "+f"(c[1]), "+f"(c[2]), "+f"(c[3])
        : "r"(a0), "r"(a1), "r"(a2), "r"(a3), "r"(b0), "r"(b1));
}

__device__ __forceinline__ void cp16(uint32_t smem_b, const void* g) {
    asm volatile("cp.async.ca.shared.global [%0], [%1], 16;"
                 :: "r"(smem_b), "l"(g));
}
#define CP_COMMIT() asm volatile("cp.async.commit_group;")
#define CP_WAIT1()  asm volatile("cp.async.wait_group 1;")

// ---- pre-round x to tf32 bits --------------------------------------------
__global__ void __launch_bounds__(256) preround_x(const float* __restrict__ x)
{
    int i = (blockIdx.x * 256 + threadIdx.x) * 4;
    float4 v = *(const float4*)&x[i];
    v.x = __uint_as_float(f2tf(v.x));
    v.y = __uint_as_float(f2tf(v.y));
    v.z = __uint_as_float(f2tf(v.z));
    v.w = __uint_as_float(f2tf(v.w));
    *(float4*)&g_X[i] = v;
}

// ================= gemm with cp.async double-buffered k-chunks ==============
// C = A @ W + bias; A:[M,K] PRE-ROUNDED tf32 bits, W:[K,N] fp32 row-major.
// CTA 128x128, 8 warps (2m x 4n), k-chunk 32.
#define GA_STR 36                       // A smem row stride (words), 36%32=4
#define GB_STR 136                      // B smem row stride (words), 136%32=8
#define G_BUFA (128*GA_STR)             // 4608 words
#define G_BUFB (32*GB_STR)              // 4352 words
#define G_BUF  (G_BUFA + G_BUFB)        // 8960 words per buffer
#define GEMM_SMEM_BYTES (2*G_BUF*4)     // 71680 B

__device__ __forceinline__ void gemm_issue_chunk(
    uint32_t sb, int buf, const float* __restrict__ A,
    const float* __restrict__ W, int m0, int n0, int kb, int K, int N, int tid)
{
    uint32_t base = sb + (uint32_t)buf * G_BUF * 4;
    #pragma unroll
    for (int j = 0; j < 4; j++) {           // A: 128x32 floats
        int pos = j * 256 + tid;
        int row = pos >> 3, c4 = (pos & 7) * 4;
        cp16(base + (row * GA_STR + c4) * 4,
             A + (size_t)(m0 + row) * K + kb + c4);
    }
    #pragma unroll
    for (int j = 0; j < 4; j++) {           // B: 32x128 floats
        int pos = j * 256 + tid;
        int row = pos >> 5, n4 = (pos & 31) * 4;
        cp16(base + (G_BUFA + row * GB_STR + n4) * 4,
             W + (size_t)(kb + row) * N + n0 + n4);
    }
}

__global__ void __launch_bounds__(256, 2) gemm_cp(
    const float* __restrict__ A, const float* __restrict__ W,
    const float* __restrict__ bias, float* __restrict__ Cout,
    int M, int N, int K, int round_out)
{
    extern __shared__ uint32_t smem[];
    uint32_t sb = (uint32_t)__cvta_generic_to_shared(smem);

    const int tid = threadIdx.x, lane = tid & 31, wid = tid >> 5;
    const int grp = lane >> 2, t4 = lane & 3;
    const int wm = wid >> 2, wn = wid & 3;
    const int m0 = blockIdx.y * 128, n0 = blockIdx.x * 128;

    float c[4][4][4];
    #pragma unroll
    for (int mi = 0; mi < 4; mi++)
        #pragma unroll
        for (int ni = 0; ni < 4; ni++)
            #pragma unroll
            for (int r = 0; r < 4; r++) c[mi][ni][r] = 0.f;

    const int nchunks = K / 32;   // 32
    gemm_issue_chunk(sb, 0, A, W, m0, n0, 0, K, N, tid);
    CP_COMMIT();
    gemm_issue_chunk(sb, 1, A, W, m0, n0, 32, K, N, tid);
    CP_COMMIT();

    for (int ci = 0; ci < nchunks; ci++) {
        const int buf = ci & 1;
        const uint32_t* As = smem + buf * G_BUF;
        const uint32_t* Bs = As + G_BUFA;
        CP_WAIT1();
        __syncthreads();

        #pragma unroll
        for (int ks = 0; ks < 4; ks++) {
            const int k0 = ks * 8;
            uint32_t a[4][4], b[4][2];
            #pragma unroll
            for (int mi = 0; mi < 4; mi++) {
                int m = wm * 64 + mi * 16 + grp;
                a[mi][0] = As[m * GA_STR + k0 + t4];
                a[mi][1] = As[(m + 8) * GA_STR + k0 + t4];
                a[mi][2] = As[m * GA_STR + k0 + t4 + 4];
                a[mi][3] = As[(m + 8) * GA_STR + k0 + t4 + 4];
            }
            #pragma unroll
            for (int ni = 0; ni < 4; ni++) {
                int n = wn * 32 + ni * 8 + grp;
                b[ni][0] = f2tf(__uint_as_float(Bs[(k0 + t4) * GB_STR + n]));
                b[ni][1] = f2tf(__uint_as_float(Bs[(k0 + t4 + 4) * GB_STR + n]));
            }
            #pragma unroll
            for (int mi = 0; mi < 4; mi++)
                #pragma unroll
                for (int ni = 0; ni < 4; ni++)
                    mma8(c[mi][ni], a[mi][0], a[mi][1], a[mi][2], a[mi][3],
                         b[ni][0], b[ni][1]);
        }
        __syncthreads();
        if (ci + 2 < nchunks)
            gemm_issue_chunk(sb, buf, A, W, m0, n0, (ci + 2) * 32, K, N, tid);
        CP_COMMIT();
    }

    #pragma unroll
    for (int mi = 0; mi < 4; mi++) {
        int r0 = m0 + wm * 64 + mi * 16 + grp;
        #pragma unroll
        for (int ni = 0; ni < 4; ni++) {
            int cb = n0 + wn * 32 + ni * 8 + 2 * t4;
            float b0 = bias[cb], b1 = bias[cb + 1];
            float v00 = c[mi][ni][0] + b0, v01 = c[mi][ni][1] + b1;
            float v10 = c[mi][ni][2] + b0, v11 = c[mi][ni][3] + b1;
            if (round_out) {
                v00 = __uint_as_float(f2tf(v00)); v01 = __uint_as_float(f2tf(v01));
                v10 = __uint_as_float(f2tf(v10)); v11 = __uint_as_float(f2tf(v11));
            }
            *(float2*)&Cout[(size_t)r0 * N + cb]       = make_float2(v00, v01);
            *(float2*)&Cout[(size_t)(r0 + 8) * N + cb] = make_float2(v10, v11);
        }
    }
}

// ================= attention pass 1 ========================================
#define A_STR  68                       // tile row stride (words), 68%32=4
#define A_TILE (128*A_STR)              // 8704 words per 128x64 tile
#define ATTN_SMEM_BYTES ((3*A_TILE + 256)*4)   // 105472 B

__device__ __forceinline__ void attn_issue_tile(
    uint32_t sb, uint32_t off_words, const float* __restrict__ src,
    int row0, int tid)
{
    #pragma unroll
    for (int j = 0; j < 8; j++) {           // 128x64 floats = 2048 x 16B
        int pos = j * 256 + tid;
        int row = pos >> 4, d4 = (pos & 15) * 4;
        cp16(sb + (off_words + row * A_STR + d4) * 4,
             src + (size_t)(row0 + row) * DM + d4);
    }
}

// c[128 a-rows][128 b-rows] += Atile . Btile^T over k=64 (raw tf32 bits)
__device__ __forceinline__ void score_mma64(
    float c[4][4][4], const uint32_t* __restrict__ Ka,
    const uint32_t* __restrict__ Qb, int wm, int wn, int grp, int t4)
{
    #pragma unroll
    for (int ks = 0; ks < 8; ks++) {
        const int k0 = ks * 8;
        uint32_t a[4][4], b[4][2];
        #pragma unroll
        for (int mi = 0; mi < 4; mi++) {
            int m = wm * 64 + mi * 16 + grp;
            a[mi][0] = Ka[m * A_STR + k0 + t4];
            a[mi][1] = Ka[(m + 8) * A_STR + k0 + t4];
            a[mi][2] = Ka[m * A_STR + k0 + t4 + 4];
            a[mi][3] = Ka[(m + 8) * A_STR + k0 + t4 + 4];
        }
        #pragma unroll
        for (int ni = 0; ni < 4; ni++) {
            int n = wn * 32 + ni * 8 + grp;
            b[ni][0] = Qb[n * A_STR + k0 + t4];
            b[ni][1] = Qb[n * A_STR + k0 + t4 + 4];
        }
        #pragma unroll
        for (int mi = 0; mi < 4; mi++)
            #pragma unroll
            for (int ni = 0; ni < 4; ni++)
                mma8(c[mi][ni], a[mi][0], a[mi][1], a[mi][2], a[mi][3],
                     b[ni][0], b[ni][1]);
    }
}

// ---- pass 1: E = exp(s/8) stored fp16; Z[tk] row sums; R = 1/Z ------------
__global__ void __launch_bounds__(256, 2) attn_z_mma()
{
    extern __shared__ uint32_t smem[];
    uint32_t sb = (uint32_t)__cvta_generic_to_shared(smem);
    const uint32_t* Ks = smem;
    float* Zs = (float*)(smem + 3 * A_TILE);

    const int tid = threadIdx.x, lane = tid & 31, wid = tid >> 5;
    const int grp = lane >> 2, t4 = lane & 3;
    const int wm = wid >> 2, wn = wid & 3;
    const int bh = blockIdx.y, b = bh >> 4, h = bh & 15;
    const int tk0 = blockIdx.x * 128;

    const float* Qb = g_Q + (size_t)b * TT * DM + h * DD;
    const float* Kb = g_K + (size_t)b * TT * DM + h * DD;
    __half* Eb = g_E + (size_t)bh * TT * TT;

    if (tid < 128) Zs[tid] = 0.f;

    // group0: K tile + Q0; group1: Q1
    attn_issue_tile(sb, 0, Kb, tk0, tid);
    attn_issue_tile(sb, A_TILE, Qb, 0, tid);
    CP_COMMIT();
    attn_issue_tile(sb, 2 * A_TILE, Qb, 128, tid);
    CP_COMMIT();

    float zacc[4][2];
    #pragma unroll
    for (int mi = 0; mi < 4; mi++) { zacc[mi][0] = 0.f; zacc[mi][1] = 0.f; }

    for (int tqc = 0; tqc < 16; tqc++) {
        const int buf = tqc & 1;
        const uint32_t* Qs = smem + (1 + buf) * A_TILE;
        CP_WAIT1();
        __syncthreads();

        float c[4][4][4];
        #pragma unroll
        for (int mi = 0; mi < 4; mi++)
            #pragma unroll
            for (int ni = 0; ni < 4; ni++)
                #pragma unroll
                for (int r = 0; r < 4; r++) c[mi][ni][r] = 0.f;

        score_mma64(c, Ks, Qs, wm, wn, grp, t4);

        #pragma unroll
        for (int mi = 0; mi < 4; mi++) {
            int tk_r = tk0 + wm * 64 + mi * 16 + grp;
            #pragma unroll
            for (int ni = 0; ni < 4; ni++) {
                int tq_c = tqc * 128 + wn * 32 + ni * 8 + 2 * t4;
                float e0 = EXPS(c[mi][ni][0]), e1 = EXPS(c[mi][ni][1]);
                float e2 = EXPS(c[mi][ni][2]), e3 = EXPS(c[mi][ni][3]);
                zacc[mi][0] += e0 + e1;
                zacc[mi][1] += e2 + e3;
                *(__half2*)&Eb[(size_t)tk_r * TT + tq_c] =
                    __floats2half2_rn(e0, e1);
                *(__half2*)&Eb[(size_t)(tk_r + 8) * TT + tq_c] =
                    __floats2half2_rn(e2, e3);
            }
        }
        __syncthreads();
        if (tqc + 2 < 16)
            attn_issue_tile(sb, (1 + buf) * A_TILE, Qb, (tqc + 2) * 128, tid);
        CP_COMMIT();
    }

    #pragma unroll
    for (int mi = 0; mi < 4; mi++)
        #pragma unroll
        for (int hf = 0; hf < 2; hf++) {
            float v = zacc[mi][hf];
            v += __shfl_xor_sync(0xffffffffu, v, 1);
            v += __shfl_xor_sync(0xffffffffu, v, 2);
            if (t4 == 0) atomicAdd(&Zs[wm * 64 + mi * 16 + grp + hf * 8], v);
        }
    __syncthreads();
    if (tid < 128) g_R[bh * TT + tk0 + tid] = 1.0f / Zs[tid];
}

// ---- pass 2: colsum[tq] = sum_tk E[tk][tq]*R[tk]; scale+round V -----------
// CTA: one (bh), 512 tq. Memory-bound reduction over the E cache.
__global__ void __launch_bounds__(256, 2) colsum_e()
{
    __shared__ float Rs[TT];     // 8 KB
    __shared__ float Cs[512];    // 2 KB

    const int tid = threadIdx.x;
    const int bh = blockIdx.y, b = bh >> 4, h = bh & 15;
    const int tq0 = blockIdx.x * 512;

    #pragma unroll
    for (int j = 0; j < 8; j++) Rs[j * 256 + tid] = g_R[bh * TT + j * 256 + tid];
    if (tid < 128) { Cs[tid * 4] = 0.f; Cs[tid * 4 + 1] = 0.f;
                     Cs[tid * 4 + 2] = 0.f; Cs[tid * 4 + 3] = 0.f; }
    __syncthreads();

    const __half* Eb = g_E + (size_t)bh * TT * TT;
    const int g = tid >> 6;                  // row group 0..3
    const int tqo = tq0 + (tid & 63) * 8;    // 8 tq per thread

    float acc[8];
    #pragma unroll
    for (int q = 0; q < 8; q++) acc[q] = 0.f;

    for (int tkb = g * 512; tkb < (g + 1) * 512; tkb += 4) {
        #pragma unroll
        for (int u = 0; u < 4; u++) {
            int tk = tkb + u;
            uint4 ev = *(const uint4*)&Eb[(size_t)tk * TT + tqo];
            float r = Rs[tk];
            const __half2* hp = (const __half2*)&ev;
            #pragma unroll
            for (int q = 0; q < 4; q++) {
                float2 f = __half22float2(hp[q]);
                acc[2 * q]     = fmaf(f.x, r, acc[2 * q]);
                acc[2 * q + 1] = fmaf(f.y, r, acc[2 * q + 1]);
            }
        }
    }

    #pragma unroll
    for (int q = 0; q < 8; q++)
        atomicAdd(&Cs[(tid & 63) * 8 + q], acc[q]);
    __syncthreads();

    // scale V rows (b, tq0..tq0+511), cols h*64..h*64+63; round to tf32
    for (int idx = tid; idx < 512 * 16; idx += 256) {
        int row = idx >> 4, c4 = (idx & 15) * 4;
        float s = Cs[row];
        float* vp = &g_V[(size_t)(b * TT + tq0 + row) * DM + h * DD + c4];
        float4 v = *(float4*)vp;
        v.x = __uint_as_float(f2tf(v.x * s));
        v.y = __uint_as_float(f2tf(v.y * s));
        v.z = __uint_as_float(f2tf(v.z * s));
        v.w = __uint_as_float(f2tf(v.w * s));
        *(float4*)vp = v;
    }
}

// ---------------- launch -----------------------------------------------------
extern "C" void kernel_launch(void* const* d_in, const int* in_sizes, int n_in,
                              void* d_out, int out_size)
{
    const float* x  = (const float*)d_in[0];
    const float* Wq = (const float*)d_in[1];
    const float* bq = (const float*)d_in[2];
    const float* Wk = (const float*)d_in[3];
    const float* bk = (const float*)d_in[4];
    const float* Wv = (const float*)d_in[5];
    const float* bv = (const float*)d_in[6];
    const float* Wo = (const float*)d_in[7];
    const float* bo = (const float*)d_in[8];
    float* out = (float*)d_out;

    float *Xp, *Qp, *Kp, *Vp;
    cudaGetSymbolAddress((void**)&Xp, g_X);
    cudaGetSymbolAddress((void**)&Qp, g_Q);
    cudaGetSymbolAddress((void**)&Kp, g_K);
    cudaGetSymbolAddress((void**)&Vp, g_V);

    cudaFuncSetAttribute(gemm_cp,
        cudaFuncAttributeMaxDynamicSharedMemorySize, GEMM_SMEM_BYTES);
    cudaFuncSetAttribute(attn_z_mma,
        cudaFuncAttributeMaxDynamicSharedMemorySize, ATTN_SMEM_BYTES);

    dim3 gproj(DM / 128, BT / 128);   // (8, 32)

    preround_x<<<(BT * DM) / 1024, 256>>>(x);
    gemm_cp<<<gproj, 256, GEMM_SMEM_BYTES>>>(Xp, Wq, bq, Qp, BT, DM, DM, 1);
    gemm_cp<<<gproj, 256, GEMM_SMEM_BYTES>>>(Xp, Wk, bk, Kp, BT, DM, DM, 1);
    gemm_cp<<<gproj, 256, GEMM_SMEM_BYTES>>>(Xp, Wv, bv, Vp, BT, DM, DM, 0);
    attn_z_mma<<<dim3(TT / 128, BHD), 256, ATTN_SMEM_BYTES>>>();
    colsum_e<<<dim3(TT / 512, BHD), 256>>>();
    gemm_cp<<<gproj, 256, GEMM_SMEM_BYTES>>>(Vp, Wo, bo, out, BT, DM, DM, 0);
}

// round 12
// speedup vs baseline: 4.9149x; 1.3649x over previous
#include <cuda_runtime.h>
#include <cuda_fp16.h>
#include <cstdint>

#define BB 2
#define TT 2048
#define HH 16
#define DD 64
#define DM 1024
#define BT (BB*TT)      // 4096
#define BHD (BB*HH)     // 32

// ---------------- static scratch ----------------
__device__ __half g_X [(size_t)BT*DM];      // 8 MB  x in fp16
__device__ __half g_Wq[(size_t)DM*DM];      // 2 MB  W^T in fp16 [n][k]
__device__ __half g_Wk[(size_t)DM*DM];
__device__ __half g_Wv[(size_t)DM*DM];
__device__ __half g_Wo[(size_t)DM*DM];
__device__ __half g_Q [(size_t)BT*DM];      // 8 MB
__device__ __half g_K [(size_t)BT*DM];      // 8 MB
__device__ __half g_V [(size_t)BT*DM];      // 8 MB
__device__ __half g_E [(size_t)BHD*TT*TT];  // 268 MB exp(s/8)
__device__ float  g_R [BHD*TT];             // 1/Z per (b,h,tk)

// ---------------- low-level helpers ----------------
__device__ __forceinline__ float ex2f(float x) {
    float r;
    asm("ex2.approx.f32 %0, %1;" : "=f"(r) : "f"(x));
    return r;
}
#define EXPS(s) ex2f((s) * 0.18033688011112042f)   // exp(s/8)

__device__ __forceinline__ void mma16(float c[4],
    uint32_t a0, uint32_t a1, uint32_t a2, uint32_t a3,
    uint32_t b0, uint32_t b1)
{
    asm volatile(
        "mma.sync.aligned.m16n8k16.row.col.f32.f16.f16.f32 "
        "{%0,%1,%2,%3}, {%4,%5,%6,%7}, {%8,%9}, {%0,%1,%2,%3};"
        : "+f"(c[0]), "+f"(c[1]), "+f"(c[2]), "+f"(c[3])
        : "r"(a0), "r"(a1), "r"(a2), "r"(a3), "r"(b0), "r"(b1));
}

__device__ __forceinline__ void cp16(uint32_t smem_b, const void* g) {
    asm volatile("cp.async.ca.shared.global [%0], [%1], 16;"
                 :: "r"(smem_b), "l"(g));
}
#define CP_COMMIT() asm volatile("cp.async.commit_group;")
#define CP_WAIT1()  asm volatile("cp.async.wait_group 1;")

// ---- one-time conversions -------------------------------------------------
__global__ void __launch_bounds__(256) conv_x(const float* __restrict__ x)
{
    int i = (blockIdx.x * 256 + threadIdx.x) * 4;
    float4 v = *(const float4*)&x[i];
    __half2 h0 = __floats2half2_rn(v.x, v.y);
    __half2 h1 = __floats2half2_rn(v.z, v.w);
    *(__half2*)&g_X[i]     = h0;
    *(__half2*)&g_X[i + 2] = h1;
}

// Wt[n][k] = (half)W[k][n]  (32x32 smem tile transpose)
__global__ void __launch_bounds__(256) conv_w(
    const float* __restrict__ W, __half* __restrict__ Wt)
{
    __shared__ float t[32][33];
    const int nb = blockIdx.x * 32, kb = blockIdx.y * 32;
    const int tx = threadIdx.x & 31, ty = threadIdx.x >> 5;
    #pragma unroll
    for (int j = 0; j < 32; j += 8)
        t[ty + j][tx] = W[(size_t)(kb + ty + j) * DM + nb + tx];   // t[k][n]
    __syncthreads();
    #pragma unroll
    for (int j = 0; j < 32; j += 8)
        Wt[(size_t)(nb + ty + j) * DM + kb + tx] = __float2half(t[tx][ty + j]);
}

// ================= fp16 gemm, cp.async double-buffered k-chunks =============
// C = A @ W + bias; A:[M,K] half row-major, Wt:[N,K] half (W transposed).
// CTA 128x128, 8 warps (2m x 4n), k-chunk 32 halves, mma m16n8k16.
#define GS 40                            // smem row stride in halves (20 words)
#define G_TILE (128*GS)                  // halves per 128x32 tile
#define G_BUF  (2*G_TILE)                // A + B per buffer
#define GEMM_SMEM_BYTES (2*G_BUF*2)      // 40960 B

__device__ __forceinline__ void gemm_issue_chunk(
    uint32_t sb, int buf, const __half* __restrict__ A,
    const __half* __restrict__ Wt, int m0, int n0, int kb, int K, int tid)
{
    uint32_t base = sb + (uint32_t)buf * G_BUF * 2;
    #pragma unroll
    for (int j = 0; j < 2; j++) {           // A: 128 rows x 32 halves
        int pos = j * 256 + tid;            // 0..511
        int row = pos >> 2, c8 = (pos & 3) * 8;
        cp16(base + (row * GS + c8) * 2,
             A + (size_t)(m0 + row) * K + kb + c8);
    }
    #pragma unroll
    for (int j = 0; j < 2; j++) {           // B: 128 n-rows x 32 halves (Wt)
        int pos = j * 256 + tid;
        int row = pos >> 2, c8 = (pos & 3) * 8;
        cp16(base + (G_TILE + row * GS + c8) * 2,
             Wt + (size_t)(n0 + row) * K + kb + c8);
    }
}

__global__ void __launch_bounds__(256, 2) gemm_h(
    const __half* __restrict__ A, const __half* __restrict__ Wt,
    const float* __restrict__ bias, __half* __restrict__ CoutH,
    float* __restrict__ CoutF, int M, int N, int K)
{
    extern __shared__ __half smem[];
    uint32_t sb = (uint32_t)__cvta_generic_to_shared(smem);

    const int tid = threadIdx.x, lane = tid & 31, wid = tid >> 5;
    const int grp = lane >> 2, t4 = lane & 3;
    const int wm = wid >> 2, wn = wid & 3;
    const int m0 = blockIdx.y * 128, n0 = blockIdx.x * 128;

    float c[4][4][4];
    #pragma unroll
    for (int mi = 0; mi < 4; mi++)
        #pragma unroll
        for (int ni = 0; ni < 4; ni++)
            #pragma unroll
            for (int r = 0; r < 4; r++) c[mi][ni][r] = 0.f;

    const int nchunks = K / 32;
    gemm_issue_chunk(sb, 0, A, Wt, m0, n0, 0, K, tid);
    CP_COMMIT();
    gemm_issue_chunk(sb, 1, A, Wt, m0, n0, 32, K, tid);
    CP_COMMIT();

    for (int ci = 0; ci < nchunks; ci++) {
        const int buf = ci & 1;
        const __half* As = smem + buf * G_BUF;
        const __half* Bs = As + G_TILE;
        CP_WAIT1();
        __syncthreads();

        #pragma unroll
        for (int ks = 0; ks < 2; ks++) {     // two k16 steps per 32-chunk
            const int k0 = ks * 16;
            uint32_t a[4][4], b[4][2];
            #pragma unroll
            for (int mi = 0; mi < 4; mi++) {
                int m = wm * 64 + mi * 16 + grp;
                a[mi][0] = *(const uint32_t*)&As[m * GS + k0 + 2 * t4];
                a[mi][1] = *(const uint32_t*)&As[(m + 8) * GS + k0 + 2 * t4];
                a[mi][2] = *(const uint32_t*)&As[m * GS + k0 + 2 * t4 + 8];
                a[mi][3] = *(const uint32_t*)&As[(m + 8) * GS + k0 + 2 * t4 + 8];
            }
            #pragma unroll
            for (int ni = 0; ni < 4; ni++) {
                int n = wn * 32 + ni * 8 + grp;
                b[ni][0] = *(const uint32_t*)&Bs[n * GS + k0 + 2 * t4];
                b[ni][1] = *(const uint32_t*)&Bs[n * GS + k0 + 2 * t4 + 8];
            }
            #pragma unroll
            for (int mi = 0; mi < 4; mi++)
                #pragma unroll
                for (int ni = 0; ni < 4; ni++)
                    mma16(c[mi][ni], a[mi][0], a[mi][1], a[mi][2], a[mi][3],
                          b[ni][0], b[ni][1]);
        }
        __syncthreads();
        if (ci + 2 < nchunks)
            gemm_issue_chunk(sb, buf, A, Wt, m0, n0, (ci + 2) * 32, K, tid);
        CP_COMMIT();
    }

    #pragma unroll
    for (int mi = 0; mi < 4; mi++) {
        int r0 = m0 + wm * 64 + mi * 16 + grp;
        #pragma unroll
        for (int ni = 0; ni < 4; ni++) {
            int cb = n0 + wn * 32 + ni * 8 + 2 * t4;
            float b0 = bias[cb], b1 = bias[cb + 1];
            float v00 = c[mi][ni][0] + b0, v01 = c[mi][ni][1] + b1;
            float v10 = c[mi][ni][2] + b0, v11 = c[mi][ni][3] + b1;
            if (CoutH) {
                *(__half2*)&CoutH[(size_t)r0 * N + cb]       = __floats2half2_rn(v00, v01);
                *(__half2*)&CoutH[(size_t)(r0 + 8) * N + cb] = __floats2half2_rn(v10, v11);
            } else {
                *(float2*)&CoutF[(size_t)r0 * N + cb]       = make_float2(v00, v01);
                *(float2*)&CoutF[(size_t)(r0 + 8) * N + cb] = make_float2(v10, v11);
            }
        }
    }
}

// ================= attention pass 1 ========================================
#define A_STR  72                        // tile row stride in halves (36 words)
#define A_TILE (128*A_STR)               // 9216 halves per 128x64 tile
#define ATTN_SMEM_BYTES ((3*A_TILE + 512)*2)    // ~56 KB

__device__ __forceinline__ void attn_issue_tile(
    uint32_t sb, uint32_t off_halves, const __half* __restrict__ src,
    int row0, int tid)
{
    #pragma unroll
    for (int j = 0; j < 4; j++) {            // 128 rows x 64 halves = 1024x16B
        int pos = j * 256 + tid;
        int row = pos >> 3, d8 = (pos & 7) * 8;
        cp16(sb + (off_halves + row * A_STR + d8) * 2,
             src + (size_t)(row0 + row) * DM + d8);
    }
}

// c[128 K-rows][128 Q-rows] += Ktile . Qtile^T over d=64 (fp16)
__device__ __forceinline__ void score_mma64(
    float c[4][4][4], const __half* __restrict__ Ka,
    const __half* __restrict__ Qb, int wm, int wn, int grp, int t4)
{
    #pragma unroll
    for (int ks = 0; ks < 4; ks++) {
        const int k0 = ks * 16;
        uint32_t a[4][4], b[4][2];
        #pragma unroll
        for (int mi = 0; mi < 4; mi++) {
            int m = wm * 64 + mi * 16 + grp;
            a[mi][0] = *(const uint32_t*)&Ka[m * A_STR + k0 + 2 * t4];
            a[mi][1] = *(const uint32_t*)&Ka[(m + 8) * A_STR + k0 + 2 * t4];
            a[mi][2] = *(const uint32_t*)&Ka[m * A_STR + k0 + 2 * t4 + 8];
            a[mi][3] = *(const uint32_t*)&Ka[(m + 8) * A_STR + k0 + 2 * t4 + 8];
        }
        #pragma unroll
        for (int ni = 0; ni < 4; ni++) {
            int n = wn * 32 + ni * 8 + grp;
            b[ni][0] = *(const uint32_t*)&Qb[n * A_STR + k0 + 2 * t4];
            b[ni][1] = *(const uint32_t*)&Qb[n * A_STR + k0 + 2 * t4 + 8];
        }
        #pragma unroll
        for (int mi = 0; mi < 4; mi++)
            #pragma unroll
            for (int ni = 0; ni < 4; ni++)
                mma16(c[mi][ni], a[mi][0], a[mi][1], a[mi][2], a[mi][3],
                      b[ni][0], b[ni][1]);
    }
}

// ---- pass 1: E = exp(s/8) stored fp16; Z[tk] row sums; R = 1/Z ------------
__global__ void __launch_bounds__(256, 2) attn_z_mma()
{
    extern __shared__ __half smem[];
    uint32_t sb = (uint32_t)__cvta_generic_to_shared(smem);
    const __half* Ks = smem;
    float* Zs = (float*)(smem + 3 * A_TILE);

    const int tid = threadIdx.x, lane = tid & 31, wid = tid >> 5;
    const int grp = lane >> 2, t4 = lane & 3;
    const int wm = wid >> 2, wn = wid & 3;
    const int bh = blockIdx.y, b = bh >> 4, h = bh & 15;
    const int tk0 = blockIdx.x * 128;

    const __half* Qb = g_Q + (size_t)b * TT * DM + h * DD;
    const __half* Kb = g_K + (size_t)b * TT * DM + h * DD;
    __half* Eb = g_E + (size_t)bh * TT * TT;

    if (tid < 128) Zs[tid] = 0.f;

    attn_issue_tile(sb, 0, Kb, tk0, tid);
    attn_issue_tile(sb, A_TILE, Qb, 0, tid);
    CP_COMMIT();
    attn_issue_tile(sb, 2 * A_TILE, Qb, 128, tid);
    CP_COMMIT();

    float zacc[4][2];
    #pragma unroll
    for (int mi = 0; mi < 4; mi++) { zacc[mi][0] = 0.f; zacc[mi][1] = 0.f; }

    for (int tqc = 0; tqc < 16; tqc++) {
        const int buf = tqc & 1;
        const __half* Qs = smem + (1 + buf) * A_TILE;
        CP_WAIT1();
        __syncthreads();

        float c[4][4][4];
        #pragma unroll
        for (int mi = 0; mi < 4; mi++)
            #pragma unroll
            for (int ni = 0; ni < 4; ni++)
                #pragma unroll
                for (int r = 0; r < 4; r++) c[mi][ni][r] = 0.f;

        score_mma64(c, Ks, Qs, wm, wn, grp, t4);

        #pragma unroll
        for (int mi = 0; mi < 4; mi++) {
            int tk_r = tk0 + wm * 64 + mi * 16 + grp;
            #pragma unroll
            for (int ni = 0; ni < 4; ni++) {
                int tq_c = tqc * 128 + wn * 32 + ni * 8 + 2 * t4;
                float e0 = EXPS(c[mi][ni][0]), e1 = EXPS(c[mi][ni][1]);
                float e2 = EXPS(c[mi][ni][2]), e3 = EXPS(c[mi][ni][3]);
                zacc[mi][0] += e0 + e1;
                zacc[mi][1] += e2 + e3;
                *(__half2*)&Eb[(size_t)tk_r * TT + tq_c] =
                    __floats2half2_rn(e0, e1);
                *(__half2*)&Eb[(size_t)(tk_r + 8) * TT + tq_c] =
                    __floats2half2_rn(e2, e3);
            }
        }
        __syncthreads();
        if (tqc + 2 < 16)
            attn_issue_tile(sb, (1 + buf) * A_TILE, Qb, (tqc + 2) * 128, tid);
        CP_COMMIT();
    }

    #pragma unroll
    for (int mi = 0; mi < 4; mi++)
        #pragma unroll
        for (int hf = 0; hf < 2; hf++) {
            float v = zacc[mi][hf];
            v += __shfl_xor_sync(0xffffffffu, v, 1);
            v += __shfl_xor_sync(0xffffffffu, v, 2);
            if (t4 == 0) atomicAdd(&Zs[wm * 64 + mi * 16 + grp + hf * 8], v);
        }
    __syncthreads();
    if (tid < 128) g_R[bh * TT + tk0 + tid] = 1.0f / Zs[tid];
}

// ---- pass 2: colsum[tq] = sum_tk E[tk][tq]*R[tk]; scale V (half) ----------
__global__ void __launch_bounds__(256, 2) colsum_e()
{
    __shared__ float Rs[TT];     // 8 KB
    __shared__ float Cs[512];    // 2 KB

    const int tid = threadIdx.x;
    const int bh = blockIdx.y, b = bh >> 4, h = bh & 15;
    const int tq0 = blockIdx.x * 512;

    #pragma unroll
    for (int j = 0; j < 8; j++) Rs[j * 256 + tid] = g_R[bh * TT + j * 256 + tid];
    if (tid < 128) { Cs[tid * 4] = 0.f; Cs[tid * 4 + 1] = 0.f;
                     Cs[tid * 4 + 2] = 0.f; Cs[tid * 4 + 3] = 0.f; }
    __syncthreads();

    const __half* Eb = g_E + (size_t)bh * TT * TT;
    const int g = tid >> 6;
    const int tqo = tq0 + (tid & 63) * 8;

    float acc[8];
    #pragma unroll
    for (int q = 0; q < 8; q++) acc[q] = 0.f;

    for (int tkb = g * 512; tkb < (g + 1) * 512; tkb += 4) {
        #pragma unroll
        for (int u = 0; u < 4; u++) {
            int tk = tkb + u;
            uint4 ev = *(const uint4*)&Eb[(size_t)tk * TT + tqo];
            float r = Rs[tk];
            const __half2* hp = (const __half2*)&ev;
            #pragma unroll
            for (int q = 0; q < 4; q++) {
                float2 f = __half22float2(hp[q]);
                acc[2 * q]     = fmaf(f.x, r, acc[2 * q]);
                acc[2 * q + 1] = fmaf(f.y, r, acc[2 * q + 1]);
            }
        }
    }

    #pragma unroll
    for (int q = 0; q < 8; q++)
        atomicAdd(&Cs[(tid & 63) * 8 + q], acc[q]);
    __syncthreads();

    // scale V rows (b, tq0..tq0+511), cols h*64..h*64+63 (half, in place)
    for (int idx = tid; idx < 512 * 8; idx += 256) {
        int row = idx >> 3, c8 = (idx & 7) * 8;
        float s = Cs[row];
        __half* vp = &g_V[(size_t)(b * TT + tq0 + row) * DM + h * DD + c8];
        uint4 hv = *(uint4*)vp;
        __half2* hp = (__half2*)&hv;
        #pragma unroll
        for (int q = 0; q < 4; q++) {
            float2 f = __half22float2(hp[q]);
            hp[q] = __floats2half2_rn(f.x * s, f.y * s);
        }
        *(uint4*)vp = hv;
    }
}

// ---------------- launch -----------------------------------------------------
extern "C" void kernel_launch(void* const* d_in, const int* in_sizes, int n_in,
                              void* d_out, int out_size)
{
    const float* x  = (const float*)d_in[0];
    const float* Wq = (const float*)d_in[1];
    const float* bq = (const float*)d_in[2];
    const float* Wk = (const float*)d_in[3];
    const float* bk = (const float*)d_in[4];
    const float* Wv = (const float*)d_in[5];
    const float* bv = (const float*)d_in[6];
    const float* Wo = (const float*)d_in[7];
    const float* bo = (const float*)d_in[8];
    float* out = (float*)d_out;

    __half *Xp, *Wqp, *Wkp, *Wvp, *Wop, *Qp, *Kp, *Vp;
    cudaGetSymbolAddress((void**)&Xp,  g_X);
    cudaGetSymbolAddress((void**)&Wqp, g_Wq);
    cudaGetSymbolAddress((void**)&Wkp, g_Wk);
    cudaGetSymbolAddress((void**)&Wvp, g_Wv);
    cudaGetSymbolAddress((void**)&Wop, g_Wo);
    cudaGetSymbolAddress((void**)&Qp,  g_Q);
    cudaGetSymbolAddress((void**)&Kp,  g_K);
    cudaGetSymbolAddress((void**)&Vp,  g_V);

    cudaFuncSetAttribute(gemm_h,
        cudaFuncAttributeMaxDynamicSharedMemorySize, GEMM_SMEM_BYTES);
    cudaFuncSetAttribute(attn_z_mma,
        cudaFuncAttributeMaxDynamicSharedMemorySize, ATTN_SMEM_BYTES);

    dim3 gproj(DM / 128, BT / 128);   // (8, 32)
    dim3 gw(DM / 32, DM / 32);        // (32, 32)

    conv_x<<<(BT * DM) / 1024, 256>>>(x);
    conv_w<<<gw, 256>>>(Wq, Wqp);
    conv_w<<<gw, 256>>>(Wk, Wkp);
    conv_w<<<gw, 256>>>(Wv, Wvp);
    conv_w<<<gw, 256>>>(Wo, Wop);
    gemm_h<<<gproj, 256, GEMM_SMEM_BYTES>>>(Xp, Wqp, bq, Qp, nullptr, BT, DM, DM);
    gemm_h<<<gproj, 256, GEMM_SMEM_BYTES>>>(Xp, Wkp, bk, Kp, nullptr, BT, DM, DM);
    gemm_h<<<gproj, 256, GEMM_SMEM_BYTES>>>(Xp, Wvp, bv, Vp, nullptr, BT, DM, DM);
    attn_z_mma<<<dim3(TT / 128, BHD), 256, ATTN_SMEM_BYTES>>>();
    colsum_e<<<dim3(TT / 512, BHD), 256>>>();
    gemm_h<<<gproj, 256, GEMM_SMEM_BYTES>>>(Vp, Wop, bo, nullptr, out, BT, DM, DM);
}

// round 13
// speedup vs baseline: 5.6830x; 1.1563x over previous
#include <cuda_runtime.h>
#include <cuda_fp16.h>
#include <cstdint>

#define BB 2
#define TT 2048
#define HH 16
#define DD 64
#define DM 1024
#define BT (BB*TT)      // 4096
#define BHD (BB*HH)     // 32

// ---------------- static scratch ----------------
__device__ __half g_X [(size_t)BT*DM];      // 8 MB  x in fp16
__device__ __half g_Wq[(size_t)DM*DM];      // 2 MB  W^T in fp16 [n][k]
__device__ __half g_Wk[(size_t)DM*DM];
__device__ __half g_Wv[(size_t)DM*DM];
__device__ __half g_Wo[(size_t)DM*DM];
__device__ __half g_Q [(size_t)BT*DM];      // 8 MB
__device__ __half g_K [(size_t)BT*DM];      // 8 MB
__device__ __half g_V [(size_t)BT*DM];      // 8 MB
__device__ __half g_E [(size_t)BHD*TT*TT];  // 268 MB exp(s/8)
__device__ float  g_R [BHD*TT];             // 1/Z per (b,h,tk)

// ---------------- low-level helpers ----------------
__device__ __forceinline__ float ex2f(float x) {
    float r;
    asm("ex2.approx.f32 %0, %1;" : "=f"(r) : "f"(x));
    return r;
}
#define EXPS(s) ex2f((s) * 0.18033688011112042f)   // exp(s/8)

__device__ __forceinline__ void mma16(float c[4],
    uint32_t a0, uint32_t a1, uint32_t a2, uint32_t a3,
    uint32_t b0, uint32_t b1)
{
    asm volatile(
        "mma.sync.aligned.m16n8k16.row.col.f32.f16.f16.f32 "
        "{%0,%1,%2,%3}, {%4,%5,%6,%7}, {%8,%9}, {%0,%1,%2,%3};"
        : "+f"(c[0]), "+f"(c[1]), "+f"(c[2]), "+f"(c[3])
        : "r"(a0), "r"(a1), "r"(a2), "r"(a3), "r"(b0), "r"(b1));
}

__device__ __forceinline__ void ldsm4(uint32_t r[4], uint32_t addr) {
    asm volatile("ldmatrix.sync.aligned.m8n8.x4.shared.b16 {%0,%1,%2,%3}, [%4];"
        : "=r"(r[0]), "=r"(r[1]), "=r"(r[2]), "=r"(r[3]) : "r"(addr));
}

__device__ __forceinline__ void cp16(uint32_t smem_b, const void* g) {
    asm volatile("cp.async.ca.shared.global [%0], [%1], 16;"
                 :: "r"(smem_b), "l"(g));
}
#define CP_COMMIT() asm volatile("cp.async.commit_group;")
#define CP_WAIT1()  asm volatile("cp.async.wait_group 1;")

// ---- one-time conversions -------------------------------------------------
__global__ void __launch_bounds__(256) conv_x(const float* __restrict__ x)
{
    int i = (blockIdx.x * 256 + threadIdx.x) * 4;
    float4 v = *(const float4*)&x[i];
    *(__half2*)&g_X[i]     = __floats2half2_rn(v.x, v.y);
    *(__half2*)&g_X[i + 2] = __floats2half2_rn(v.z, v.w);
}

// Wt[n][k] = (half)W[k][n], all four weights in one launch (grid.z = which)
__global__ void __launch_bounds__(256) conv_w4(
    const float* __restrict__ W0, const float* __restrict__ W1,
    const float* __restrict__ W2, const float* __restrict__ W3)
{
    __shared__ float t[32][33];
    const float* src; __half* dst;
    switch (blockIdx.z) {
        case 0:  src = W0; dst = g_Wq; break;
        case 1:  src = W1; dst = g_Wk; break;
        case 2:  src = W2; dst = g_Wv; break;
        default: src = W3; dst = g_Wo; break;
    }
    const int nb = blockIdx.x * 32, kb = blockIdx.y * 32;
    const int tx = threadIdx.x & 31, ty = threadIdx.x >> 5;
    #pragma unroll
    for (int j = 0; j < 32; j += 8)
        t[ty + j][tx] = src[(size_t)(kb + ty + j) * DM + nb + tx];   // t[k][n]
    __syncthreads();
    #pragma unroll
    for (int j = 0; j < 32; j += 8)
        dst[(size_t)(nb + ty + j) * DM + kb + tx] = __float2half(t[tx][ty + j]);
}

// ================= fp16 gemm, cp.async double-buffered, k-chunk 64 =========
// C = A @ W + bias; A:[M,K] half row-major, Wt:[N,K] half (W transposed).
// CTA 128x128, 8 warps (2m x 4n), mma m16n8k16, ldmatrix fragment loads.
#define GS 72                            // smem row stride in halves
#define G_TILE (128*GS)                  // halves per 128x64 tile
#define G_BUF  (2*G_TILE)                // A + B per buffer
#define GEMM_SMEM_BYTES (2*G_BUF*2)      // 73728 B

__device__ __forceinline__ void gemm_issue_chunk(
    uint32_t sb, int buf, const __half* __restrict__ A,
    const __half* __restrict__ Wt, int m0, int n0, int kb, int K, int tid)
{
    uint32_t base = sb + (uint32_t)buf * G_BUF * 2;
    #pragma unroll
    for (int j = 0; j < 4; j++) {           // A: 128 rows x 64 halves
        int pos = j * 256 + tid;            // 0..1023
        int row = pos >> 3, c8 = (pos & 7) * 8;
        cp16(base + (row * GS + c8) * 2,
             A + (size_t)(m0 + row) * K + kb + c8);
    }
    #pragma unroll
    for (int j = 0; j < 4; j++) {           // B: 128 n-rows x 64 halves
        int pos = j * 256 + tid;
        int row = pos >> 3, c8 = (pos & 7) * 8;
        cp16(base + (G_TILE + row * GS + c8) * 2,
             Wt + (size_t)(n0 + row) * K + kb + c8);
    }
}

__global__ void __launch_bounds__(256, 2) gemm_h(
    const __half* __restrict__ A, const __half* __restrict__ Wt,
    const float* __restrict__ bias, __half* __restrict__ CoutH,
    float* __restrict__ CoutF, int M, int N, int K)
{
    extern __shared__ __half smem[];
    uint32_t sb = (uint32_t)__cvta_generic_to_shared(smem);

    const int tid = threadIdx.x, lane = tid & 31, wid = tid >> 5;
    const int grp = lane >> 2, t4 = lane & 3;
    const int lr = lane & 7, lq = lane >> 3;
    const int wm = wid >> 2, wn = wid & 3;
    const int m0 = blockIdx.y * 128, n0 = blockIdx.x * 128;

    float c[4][4][4];
    #pragma unroll
    for (int mi = 0; mi < 4; mi++)
        #pragma unroll
        for (int ni = 0; ni < 4; ni++)
            #pragma unroll
            for (int r = 0; r < 4; r++) c[mi][ni][r] = 0.f;

    const int nchunks = K / 64;
    gemm_issue_chunk(sb, 0, A, Wt, m0, n0, 0, K, tid);
    CP_COMMIT();
    gemm_issue_chunk(sb, 1, A, Wt, m0, n0, 64, K, tid);
    CP_COMMIT();

    // ldmatrix per-lane row/col offsets
    const int a_row = lr + ((lq & 1) << 3);      // + m_base
    const int a_col = (lq >> 1) << 3;            // + k0
    const int b_row = lr + ((lq >> 1) << 3);     // + n_base
    const int b_col = (lq & 1) << 3;             // + k0

    for (int ci = 0; ci < nchunks; ci++) {
        const int buf = ci & 1;
        const uint32_t As = sb + (uint32_t)buf * G_BUF * 2;
        const uint32_t Bs = As + G_TILE * 2;
        CP_WAIT1();
        __syncthreads();

        #pragma unroll
        for (int ks = 0; ks < 4; ks++) {
            const int k0 = ks * 16;
            uint32_t a[4][4], b[2][4];
            #pragma unroll
            for (int mi = 0; mi < 4; mi++)
                ldsm4(a[mi], As + ((wm * 64 + mi * 16 + a_row) * GS + k0 + a_col) * 2);
            #pragma unroll
            for (int np = 0; np < 2; np++)
                ldsm4(b[np], Bs + ((wn * 32 + np * 16 + b_row) * GS + k0 + b_col) * 2);
            #pragma unroll
            for (int mi = 0; mi < 4; mi++)
                #pragma unroll
                for (int ni = 0; ni < 4; ni++)
                    mma16(c[mi][ni], a[mi][0], a[mi][1], a[mi][2], a[mi][3],
                          b[ni >> 1][(ni & 1) * 2], b[ni >> 1][(ni & 1) * 2 + 1]);
        }
        __syncthreads();
        if (ci + 2 < nchunks)
            gemm_issue_chunk(sb, buf, A, Wt, m0, n0, (ci + 2) * 64, K, tid);
        CP_COMMIT();
    }

    #pragma unroll
    for (int mi = 0; mi < 4; mi++) {
        int r0 = m0 + wm * 64 + mi * 16 + grp;
        #pragma unroll
        for (int ni = 0; ni < 4; ni++) {
            int cb = n0 + wn * 32 + ni * 8 + 2 * t4;
            float b0 = bias[cb], b1 = bias[cb + 1];
            float v00 = c[mi][ni][0] + b0, v01 = c[mi][ni][1] + b1;
            float v10 = c[mi][ni][2] + b0, v11 = c[mi][ni][3] + b1;
            if (CoutH) {
                *(__half2*)&CoutH[(size_t)r0 * N + cb]       = __floats2half2_rn(v00, v01);
                *(__half2*)&CoutH[(size_t)(r0 + 8) * N + cb] = __floats2half2_rn(v10, v11);
            } else {
                *(float2*)&CoutF[(size_t)r0 * N + cb]       = make_float2(v00, v01);
                *(float2*)&CoutF[(size_t)(r0 + 8) * N + cb] = make_float2(v10, v11);
            }
        }
    }
}

// ================= attention pass 1 ========================================
#define A_STR  72                        // tile row stride in halves
#define A_TILE (128*A_STR)               // 9216 halves per 128x64 tile
#define ATTN_SMEM_BYTES ((3*A_TILE + 512)*2)    // ~56 KB

__device__ __forceinline__ void attn_issue_tile(
    uint32_t sb, uint32_t off_halves, const __half* __restrict__ src,
    int row0, int tid)
{
    #pragma unroll
    for (int j = 0; j < 4; j++) {            // 128 rows x 64 halves
        int pos = j * 256 + tid;
        int row = pos >> 3, d8 = (pos & 7) * 8;
        cp16(sb + (off_halves + row * A_STR + d8) * 2,
             src + (size_t)(row0 + row) * DM + d8);
    }
}

// c[128 K-rows][128 Q-rows] += Ktile . Qtile^T over d=64, ldmatrix loads
__device__ __forceinline__ void score_mma64(
    float c[4][4][4], uint32_t Ka, uint32_t Qb,
    int wm, int wn, int a_row, int a_col, int b_row, int b_col)
{
    #pragma unroll
    for (int ks = 0; ks < 4; ks++) {
        const int k0 = ks * 16;
        uint32_t a[4][4], b[2][4];
        #pragma unroll
        for (int mi = 0; mi < 4; mi++)
            ldsm4(a[mi], Ka + ((wm * 64 + mi * 16 + a_row) * A_STR + k0 + a_col) * 2);
        #pragma unroll
        for (int np = 0; np < 2; np++)
            ldsm4(b[np], Qb + ((wn * 32 + np * 16 + b_row) * A_STR + k0 + b_col) * 2);
        #pragma unroll
        for (int mi = 0; mi < 4; mi++)
            #pragma unroll
            for (int ni = 0; ni < 4; ni++)
                mma16(c[mi][ni], a[mi][0], a[mi][1], a[mi][2], a[mi][3],
                      b[ni >> 1][(ni & 1) * 2], b[ni >> 1][(ni & 1) * 2 + 1]);
    }
}

// ---- pass 1: E = exp(s/8) stored fp16; Z[tk] row sums; R = 1/Z ------------
__global__ void __launch_bounds__(256, 2) attn_z_mma()
{
    extern __shared__ __half smem[];
    uint32_t sb = (uint32_t)__cvta_generic_to_shared(smem);
    float* Zs = (float*)(smem + 3 * A_TILE);

    const int tid = threadIdx.x, lane = tid & 31, wid = tid >> 5;
    const int grp = lane >> 2, t4 = lane & 3;
    const int lr = lane & 7, lq = lane >> 3;
    const int wm = wid >> 2, wn = wid & 3;
    const int bh = blockIdx.y, b = bh >> 4, h = bh & 15;
    const int tk0 = blockIdx.x * 128;

    const int a_row = lr + ((lq & 1) << 3), a_col = (lq >> 1) << 3;
    const int b_row = lr + ((lq >> 1) << 3), b_col = (lq & 1) << 3;

    const __half* Qb = g_Q + (size_t)b * TT * DM + h * DD;
    const __half* Kb = g_K + (size_t)b * TT * DM + h * DD;
    __half* Eb = g_E + (size_t)bh * TT * TT;

    if (tid < 128) Zs[tid] = 0.f;

    attn_issue_tile(sb, 0, Kb, tk0, tid);
    attn_issue_tile(sb, A_TILE, Qb, 0, tid);
    CP_COMMIT();
    attn_issue_tile(sb, 2 * A_TILE, Qb, 128, tid);
    CP_COMMIT();

    float zacc[4][2];
    #pragma unroll
    for (int mi = 0; mi < 4; mi++) { zacc[mi][0] = 0.f; zacc[mi][1] = 0.f; }

    for (int tqc = 0; tqc < 16; tqc++) {
        const int buf = tqc & 1;
        const uint32_t Qs = sb + (uint32_t)(1 + buf) * A_TILE * 2;
        CP_WAIT1();
        __syncthreads();

        float c[4][4][4];
        #pragma unroll
        for (int mi = 0; mi < 4; mi++)
            #pragma unroll
            for (int ni = 0; ni < 4; ni++)
                #pragma unroll
                for (int r = 0; r < 4; r++) c[mi][ni][r] = 0.f;

        score_mma64(c, sb, Qs, wm, wn, a_row, a_col, b_row, b_col);

        #pragma unroll
        for (int mi = 0; mi < 4; mi++) {
            int tk_r = tk0 + wm * 64 + mi * 16 + grp;
            #pragma unroll
            for (int ni = 0; ni < 4; ni++) {
                int tq_c = tqc * 128 + wn * 32 + ni * 8 + 2 * t4;
                float e0 = EXPS(c[mi][ni][0]), e1 = EXPS(c[mi][ni][1]);
                float e2 = EXPS(c[mi][ni][2]), e3 = EXPS(c[mi][ni][3]);
                zacc[mi][0] += e0 + e1;
                zacc[mi][1] += e2 + e3;
                *(__half2*)&Eb[(size_t)tk_r * TT + tq_c] =
                    __floats2half2_rn(e0, e1);
                *(__half2*)&Eb[(size_t)(tk_r + 8) * TT + tq_c] =
                    __floats2half2_rn(e2, e3);
            }
        }
        __syncthreads();
        if (tqc + 2 < 16)
            attn_issue_tile(sb, (uint32_t)(1 + buf) * A_TILE, Qb, (tqc + 2) * 128, tid);
        CP_COMMIT();
    }

    #pragma unroll
    for (int mi = 0; mi < 4; mi++)
        #pragma unroll
        for (int hf = 0; hf < 2; hf++) {
            float v = zacc[mi][hf];
            v += __shfl_xor_sync(0xffffffffu, v, 1);
            v += __shfl_xor_sync(0xffffffffu, v, 2);
            if (t4 == 0) atomicAdd(&Zs[wm * 64 + mi * 16 + grp + hf * 8], v);
        }
    __syncthreads();
    if (tid < 128) g_R[bh * TT + tk0 + tid] = 1.0f / Zs[tid];
}

// ---- pass 2: colsum[tq] = sum_tk E[tk][tq]*R[tk]; scale V (half) ----------
__global__ void __launch_bounds__(256, 2) colsum_e()
{
    __shared__ float Rs[TT];     // 8 KB
    __shared__ float Cs[512];    // 2 KB

    const int tid = threadIdx.x;
    const int bh = blockIdx.y, b = bh >> 4, h = bh & 15;
    const int tq0 = blockIdx.x * 512;

    #pragma unroll
    for (int j = 0; j < 8; j++) Rs[j * 256 + tid] = g_R[bh * TT + j * 256 + tid];
    if (tid < 128) { Cs[tid * 4] = 0.f; Cs[tid * 4 + 1] = 0.f;
                     Cs[tid * 4 + 2] = 0.f; Cs[tid * 4 + 3] = 0.f; }
    __syncthreads();

    const __half* Eb = g_E + (size_t)bh * TT * TT;
    const int g = tid >> 6;
    const int tqo = tq0 + (tid & 63) * 8;

    float acc[8];
    #pragma unroll
    for (int q = 0; q < 8; q++) acc[q] = 0.f;

    for (int tkb = g * 512; tkb < (g + 1) * 512; tkb += 4) {
        #pragma unroll
        for (int u = 0; u < 4; u++) {
            int tk = tkb + u;
            uint4 ev = *(const uint4*)&Eb[(size_t)tk * TT + tqo];
            float r = Rs[tk];
            const __half2* hp = (const __half2*)&ev;
            #pragma unroll
            for (int q = 0; q < 4; q++) {
                float2 f = __half22float2(hp[q]);
                acc[2 * q]     = fmaf(f.x, r, acc[2 * q]);
                acc[2 * q + 1] = fmaf(f.y, r, acc[2 * q + 1]);
            }
        }
    }

    #pragma unroll
    for (int q = 0; q < 8; q++)
        atomicAdd(&Cs[(tid & 63) * 8 + q], acc[q]);
    __syncthreads();

    for (int idx = tid; idx < 512 * 8; idx += 256) {
        int row = idx >> 3, c8 = (idx & 7) * 8;
        float s = Cs[row];
        __half* vp = &g_V[(size_t)(b * TT + tq0 + row) * DM + h * DD + c8];
        uint4 hv = *(uint4*)vp;
        __half2* hp = (__half2*)&hv;
        #pragma unroll
        for (int q = 0; q < 4; q++) {
            float2 f = __half22float2(hp[q]);
            hp[q] = __floats2half2_rn(f.x * s, f.y * s);
        }
        *(uint4*)vp = hv;
    }
}

// ---------------- launch -----------------------------------------------------
extern "C" void kernel_launch(void* const* d_in, const int* in_sizes, int n_in,
                              void* d_out, int out_size)
{
    const float* x  = (const float*)d_in[0];
    const float* Wq = (const float*)d_in[1];
    const float* bq = (const float*)d_in[2];
    const float* Wk = (const float*)d_in[3];
    const float* bk = (const float*)d_in[4];
    const float* Wv = (const float*)d_in[5];
    const float* bv = (const float*)d_in[6];
    const float* Wo = (const float*)d_in[7];
    const float* bo = (const float*)d_in[8];
    float* out = (float*)d_out;

    __half *Xp, *Wqp, *Wkp, *Wvp, *Wop, *Qp, *Kp, *Vp;
    cudaGetSymbolAddress((void**)&Xp,  g_X);
    cudaGetSymbolAddress((void**)&Wqp, g_Wq);
    cudaGetSymbolAddress((void**)&Wkp, g_Wk);
    cudaGetSymbolAddress((void**)&Wvp, g_Wv);
    cudaGetSymbolAddress((void**)&Wop, g_Wo);
    cudaGetSymbolAddress((void**)&Qp,  g_Q);
    cudaGetSymbolAddress((void**)&Kp,  g_K);
    cudaGetSymbolAddress((void**)&Vp,  g_V);

    cudaFuncSetAttribute(gemm_h,
        cudaFuncAttributeMaxDynamicSharedMemorySize, GEMM_SMEM_BYTES);
    cudaFuncSetAttribute(attn_z_mma,
        cudaFuncAttributeMaxDynamicSharedMemorySize, ATTN_SMEM_BYTES);

    dim3 gproj(DM / 128, BT / 128);   // (8, 32)

    conv_x<<<(BT * DM) / 1024, 256>>>(x);
    conv_w4<<<dim3(DM / 32, DM / 32, 4), 256>>>(Wq, Wk, Wv, Wo);
    gemm_h<<<gproj, 256, GEMM_SMEM_BYTES>>>(Xp, Wqp, bq, Qp, nullptr, BT, DM, DM);
    gemm_h<<<gproj, 256, GEMM_SMEM_BYTES>>>(Xp, Wkp, bk, Kp, nullptr, BT, DM, DM);
    gemm_h<<<gproj, 256, GEMM_SMEM_BYTES>>>(Xp, Wvp, bv, Vp, nullptr, BT, DM, DM);
    attn_z_mma<<<dim3(TT / 128, BHD), 256, ATTN_SMEM_BYTES>>>();
    colsum_e<<<dim3(TT / 512, BHD), 256>>>();
    gemm_h<<<gproj, 256, GEMM_SMEM_BYTES>>>(Vp, Wop, bo, nullptr, out, BT, DM, DM);
}

// round 16
// speedup vs baseline: 5.8121x; 1.0227x over previous
#include <cuda_runtime.h>
#include <cuda_fp16.h>
#include <cstdint>

#define BB 2
#define TT 2048
#define HH 16
#define DD 64
#define DM 1024
#define BT (BB*TT)      // 4096
#define BHD (BB*HH)     // 32

// ---------------- static scratch ----------------
__device__ __half g_X [(size_t)BT*DM];      // 8 MB  x in fp16
__device__ __half g_Wq[(size_t)DM*DM];      // 2 MB  W^T in fp16 [n][k]
__device__ __half g_Wk[(size_t)DM*DM];
__device__ __half g_Wv[(size_t)DM*DM];
__device__ __half g_Wo[(size_t)DM*DM];
__device__ __half g_Q [(size_t)BT*DM];      // 8 MB
__device__ __half g_K [(size_t)BT*DM];      // 8 MB
__device__ __half g_V [(size_t)BT*DM];      // 8 MB
__device__ __half g_E [(size_t)BHD*TT*TT];  // 268 MB exp(s/8)
__device__ float  g_R [BHD*TT];             // 1/Z per (b,h,tk)

// ---------------- low-level helpers ----------------
__device__ __forceinline__ float ex2f(float x) {
    float r;
    asm("ex2.approx.f32 %0, %1;" : "=f"(r) : "f"(x));
    return r;
}
#define EXPS(s) ex2f((s) * 0.18033688011112042f)   // exp(s/8)

__device__ __forceinline__ void mma16(float c[4],
    uint32_t a0, uint32_t a1, uint32_t a2, uint32_t a3,
    uint32_t b0, uint32_t b1)
{
    asm volatile(
        "mma.sync.aligned.m16n8k16.row.col.f32.f16.f16.f32 "
        "{%0,%1,%2,%3}, {%4,%5,%6,%7}, {%8,%9}, {%0,%1,%2,%3};"
        : "+f"(c[0]), "+f"(c[1]), "+f"(c[2]), "+f"(c[3])
        : "r"(a0), "r"(a1), "r"(a2), "r"(a3), "r"(b0), "r"(b1));
}

__device__ __forceinline__ void ldsm4(uint32_t r[4], uint32_t addr) {
    asm volatile("ldmatrix.sync.aligned.m8n8.x4.shared.b16 {%0,%1,%2,%3}, [%4];"
        : "=r"(r[0]), "=r"(r[1]), "=r"(r[2]), "=r"(r[3]) : "r"(addr));
}

__device__ __forceinline__ void cp16(uint32_t smem_b, const void* g) {
    asm volatile("cp.async.ca.shared.global [%0], [%1], 16;"
                 :: "r"(smem_b), "l"(g));
}
#define CP_COMMIT() asm volatile("cp.async.commit_group;")
#define CP_WAIT1()  asm volatile("cp.async.wait_group 1;")

// ---- one-time conversions -------------------------------------------------
__global__ void __launch_bounds__(256) conv_x(const float* __restrict__ x)
{
    int i = (blockIdx.x * 256 + threadIdx.x) * 4;
    float4 v = *(const float4*)&x[i];
    *(__half2*)&g_X[i]     = __floats2half2_rn(v.x, v.y);
    *(__half2*)&g_X[i + 2] = __floats2half2_rn(v.z, v.w);
}

// Wt[n][k] = (half)W[k][n], all four weights in one launch (grid.z = which)
__global__ void __launch_bounds__(256) conv_w4(
    const float* __restrict__ W0, const float* __restrict__ W1,
    const float* __restrict__ W2, const float* __restrict__ W3)
{
    __shared__ float t[32][33];
    const float* src; __half* dst;
    switch (blockIdx.z) {
        case 0:  src = W0; dst = g_Wq; break;
        case 1:  src = W1; dst = g_Wk; break;
        case 2:  src = W2; dst = g_Wv; break;
        default: src = W3; dst = g_Wo; break;
    }
    const int nb = blockIdx.x * 32, kb = blockIdx.y * 32;
    const int tx = threadIdx.x & 31, ty = threadIdx.x >> 5;
    #pragma unroll
    for (int j = 0; j < 32; j += 8)
        t[ty + j][tx] = src[(size_t)(kb + ty + j) * DM + nb + tx];   // t[k][n]
    __syncthreads();
    #pragma unroll
    for (int j = 0; j < 32; j += 8)
        dst[(size_t)(nb + ty + j) * DM + kb + tx] = __float2half(t[tx][ty + j]);
}

// ================= fp16 gemm core, cp.async double-buffered, k-chunk 64 ====
// C = A @ W + bias; A:[M,K] half row-major, Wt:[N,K] half (W transposed).
// CTA 128x128, 8 warps (2m x 4n), mma m16n8k16, ldmatrix fragment loads.
#define GS 72                            // smem row stride in halves
#define G_TILE (128*GS)                  // halves per 128x64 tile
#define G_BUF  (2*G_TILE)                // A + B per buffer
#define GEMM_SMEM_BYTES (2*G_BUF*2)      // 73728 B

__device__ __forceinline__ void gemm_issue_chunk(
    uint32_t sb, int buf, const __half* __restrict__ A,
    const __half* __restrict__ Wt, int m0, int n0, int kb, int K, int tid)
{
    uint32_t base = sb + (uint32_t)buf * G_BUF * 2;
    #pragma unroll
    for (int j = 0; j < 4; j++) {           // A: 128 rows x 64 halves
        int pos = j * 256 + tid;            // 0..1023
        int row = pos >> 3, c8 = (pos & 7) * 8;
        cp16(base + (row * GS + c8) * 2,
             A + (size_t)(m0 + row) * K + kb + c8);
    }
    #pragma unroll
    for (int j = 0; j < 4; j++) {           // B: 128 n-rows x 64 halves
        int pos = j * 256 + tid;
        int row = pos >> 3, c8 = (pos & 7) * 8;
        cp16(base + (G_TILE + row * GS + c8) * 2,
             Wt + (size_t)(n0 + row) * K + kb + c8);
    }
}

__device__ __forceinline__ void gemm_core(
    const __half* __restrict__ A, const __half* __restrict__ Wt,
    const float* __restrict__ bias, __half* __restrict__ CoutH,
    float* __restrict__ CoutF, int M, int N, int K, int m0, int n0)
{
    extern __shared__ __half smem[];
    uint32_t sb = (uint32_t)__cvta_generic_to_shared(smem);

    const int tid = threadIdx.x, lane = tid & 31, wid = tid >> 5;
    const int grp = lane >> 2, t4 = lane & 3;
    const int lr = lane & 7, lq = lane >> 3;
    const int wm = wid >> 2, wn = wid & 3;

    float c[4][4][4];
    #pragma unroll
    for (int mi = 0; mi < 4; mi++)
        #pragma unroll
        for (int ni = 0; ni < 4; ni++)
            #pragma unroll
            for (int r = 0; r < 4; r++) c[mi][ni][r] = 0.f;

    const int nchunks = K / 64;
    gemm_issue_chunk(sb, 0, A, Wt, m0, n0, 0, K, tid);
    CP_COMMIT();
    gemm_issue_chunk(sb, 1, A, Wt, m0, n0, 64, K, tid);
    CP_COMMIT();

    // ldmatrix per-lane row/col offsets
    const int a_row = lr + ((lq & 1) << 3);      // + m_base
    const int a_col = (lq >> 1) << 3;            // + k0
    const int b_row = lr + ((lq >> 1) << 3);     // + n_base
    const int b_col = (lq & 1) << 3;             // + k0

    for (int ci = 0; ci < nchunks; ci++) {
        const int buf = ci & 1;
        const uint32_t As = sb + (uint32_t)buf * G_BUF * 2;
        const uint32_t Bs = As + G_TILE * 2;
        CP_WAIT1();
        __syncthreads();

        #pragma unroll
        for (int ks = 0; ks < 4; ks++) {
            const int k0 = ks * 16;
            uint32_t a[4][4], b[2][4];
            #pragma unroll
            for (int mi = 0; mi < 4; mi++)
                ldsm4(a[mi], As + ((wm * 64 + mi * 16 + a_row) * GS + k0 + a_col) * 2);
            #pragma unroll
            for (int np = 0; np < 2; np++)
                ldsm4(b[np], Bs + ((wn * 32 + np * 16 + b_row) * GS + k0 + b_col) * 2);
            #pragma unroll
            for (int mi = 0; mi < 4; mi++)
                #pragma unroll
                for (int ni = 0; ni < 4; ni++)
                    mma16(c[mi][ni], a[mi][0], a[mi][1], a[mi][2], a[mi][3],
                          b[ni >> 1][(ni & 1) * 2], b[ni >> 1][(ni & 1) * 2 + 1]);
        }
        __syncthreads();
        if (ci + 2 < nchunks)
            gemm_issue_chunk(sb, buf, A, Wt, m0, n0, (ci + 2) * 64, K, tid);
        CP_COMMIT();
    }

    #pragma unroll
    for (int mi = 0; mi < 4; mi++) {
        int r0 = m0 + wm * 64 + mi * 16 + grp;
        #pragma unroll
        for (int ni = 0; ni < 4; ni++) {
            int cb = n0 + wn * 32 + ni * 8 + 2 * t4;
            float b0 = bias[cb], b1 = bias[cb + 1];
            float v00 = c[mi][ni][0] + b0, v01 = c[mi][ni][1] + b1;
            float v10 = c[mi][ni][2] + b0, v11 = c[mi][ni][3] + b1;
            if (CoutH) {
                *(__half2*)&CoutH[(size_t)r0 * N + cb]       = __floats2half2_rn(v00, v01);
                *(__half2*)&CoutH[(size_t)(r0 + 8) * N + cb] = __floats2half2_rn(v10, v11);
            } else {
                *(float2*)&CoutF[(size_t)r0 * N + cb]       = make_float2(v00, v01);
                *(float2*)&CoutF[(size_t)(r0 + 8) * N + cb] = make_float2(v10, v11);
            }
        }
    }
}

// fused Q/K/V projection: grid.z selects weight/bias/output
__global__ void __launch_bounds__(256, 2) gemm_qkv(
    const float* __restrict__ bq, const float* __restrict__ bk,
    const float* __restrict__ bv)
{
    const __half* Wt; const float* bias; __half* Cout;
    switch (blockIdx.z) {
        case 0:  Wt = g_Wq; bias = bq; Cout = g_Q; break;
        case 1:  Wt = g_Wk; bias = bk; Cout = g_K; break;
        default: Wt = g_Wv; bias = bv; Cout = g_V; break;
    }
    gemm_core(g_X, Wt, bias, Cout, nullptr, BT, DM, DM,
              blockIdx.y * 128, blockIdx.x * 128);
}

// final output gemm: out = Vscaled @ Wo + bo (fp32 out)
__global__ void __launch_bounds__(256, 2) gemm_out(
    const float* __restrict__ bo, float* __restrict__ out)
{
    gemm_core(g_V, g_Wo, bo, nullptr, out, BT, DM, DM,
              blockIdx.y * 128, blockIdx.x * 128);
}

// ================= attention pass 1 ========================================
#define A_STR  72
#define A_TILE (128*A_STR)
#define ATTN_SMEM_BYTES ((3*A_TILE + 512)*2)

__device__ __forceinline__ void attn_issue_tile(
    uint32_t sb, uint32_t off_halves, const __half* __restrict__ src,
    int row0, int tid)
{
    #pragma unroll
    for (int j = 0; j < 4; j++) {
        int pos = j * 256 + tid;
        int row = pos >> 3, d8 = (pos & 7) * 8;
        cp16(sb + (off_halves + row * A_STR + d8) * 2,
             src + (size_t)(row0 + row) * DM + d8);
    }
}

__device__ __forceinline__ void score_mma64(
    float c[4][4][4], uint32_t Ka, uint32_t Qb,
    int wm, int wn, int a_row, int a_col, int b_row, int b_col)
{
    #pragma unroll
    for (int ks = 0; ks < 4; ks++) {
        const int k0 = ks * 16;
        uint32_t a[4][4], b[2][4];
        #pragma unroll
        for (int mi = 0; mi < 4; mi++)
            ldsm4(a[mi], Ka + ((wm * 64 + mi * 16 + a_row) * A_STR + k0 + a_col) * 2);
        #pragma unroll
        for (int np = 0; np < 2; np++)
            ldsm4(b[np], Qb + ((wn * 32 + np * 16 + b_row) * A_STR + k0 + b_col) * 2);
        #pragma unroll
        for (int mi = 0; mi < 4; mi++)
            #pragma unroll
            for (int ni = 0; ni < 4; ni++)
                mma16(c[mi][ni], a[mi][0], a[mi][1], a[mi][2], a[mi][3],
                      b[ni >> 1][(ni & 1) * 2], b[ni >> 1][(ni & 1) * 2 + 1]);
    }
}

__global__ void __launch_bounds__(256, 2) attn_z_mma()
{
    extern __shared__ __half hsmem[];
    uint32_t sb = (uint32_t)__cvta_generic_to_shared(hsmem);
    float* Zs = (float*)(hsmem + 3 * A_TILE);

    const int tid = threadIdx.x, lane = tid & 31, wid = tid >> 5;
    const int grp = lane >> 2, t4 = lane & 3;
    const int lr = lane & 7, lq = lane >> 3;
    const int wm = wid >> 2, wn = wid & 3;
    const int bh = blockIdx.y, b = bh >> 4, h = bh & 15;
    const int tk0 = blockIdx.x * 128;

    const int a_row = lr + ((lq & 1) << 3), a_col = (lq >> 1) << 3;
    const int b_row = lr + ((lq >> 1) << 3), b_col = (lq & 1) << 3;

    const __half* Qb = g_Q + (size_t)b * TT * DM + h * DD;
    const __half* Kb = g_K + (size_t)b * TT * DM + h * DD;
    __half* Eb = g_E + (size_t)bh * TT * TT;

    if (tid < 128) Zs[tid] = 0.f;

    attn_issue_tile(sb, 0, Kb, tk0, tid);
    attn_issue_tile(sb, A_TILE, Qb, 0, tid);
    CP_COMMIT();
    attn_issue_tile(sb, 2 * A_TILE, Qb, 128, tid);
    CP_COMMIT();

    float zacc[4][2];
    #pragma unroll
    for (int mi = 0; mi < 4; mi++) { zacc[mi][0] = 0.f; zacc[mi][1] = 0.f; }

    for (int tqc = 0; tqc < 16; tqc++) {
        const int buf = tqc & 1;
        const uint32_t Qs = sb + (uint32_t)(1 + buf) * A_TILE * 2;
        CP_WAIT1();
        __syncthreads();

        float c[4][4][4];
        #pragma unroll
        for (int mi = 0; mi < 4; mi++)
            #pragma unroll
            for (int ni = 0; ni < 4; ni++)
                #pragma unroll
                for (int r = 0; r < 4; r++) c[mi][ni][r] = 0.f;

        score_mma64(c, sb, Qs, wm, wn, a_row, a_col, b_row, b_col);

        #pragma unroll
        for (int mi = 0; mi < 4; mi++) {
            int tk_r = tk0 + wm * 64 + mi * 16 + grp;
            #pragma unroll
            for (int ni = 0; ni < 4; ni++) {
                int tq_c = tqc * 128 + wn * 32 + ni * 8 + 2 * t4;
                float e0 = EXPS(c[mi][ni][0]), e1 = EXPS(c[mi][ni][1]);
                float e2 = EXPS(c[mi][ni][2]), e3 = EXPS(c[mi][ni][3]);
                zacc[mi][0] += e0 + e1;
                zacc[mi][1] += e2 + e3;
                *(__half2*)&Eb[(size_t)tk_r * TT + tq_c] =
                    __floats2half2_rn(e0, e1);
                *(__half2*)&Eb[(size_t)(tk_r + 8) * TT + tq_c] =
                    __floats2half2_rn(e2, e3);
            }
        }
        __syncthreads();
        if (tqc + 2 < 16)
            attn_issue_tile(sb, (uint32_t)(1 + buf) * A_TILE, Qb, (tqc + 2) * 128, tid);
        CP_COMMIT();
    }

    #pragma unroll
    for (int mi = 0; mi < 4; mi++)
        #pragma unroll
        for (int hf = 0; hf < 2; hf++) {
            float v = zacc[mi][hf];
            v += __shfl_xor_sync(0xffffffffu, v, 1);
            v += __shfl_xor_sync(0xffffffffu, v, 2);
            if (t4 == 0) atomicAdd(&Zs[wm * 64 + mi * 16 + grp + hf * 8], v);
        }
    __syncthreads();
    if (tid < 128) g_R[bh * TT + tk0 + tid] = 1.0f / Zs[tid];
}

// ---- pass 2: colsum[tq] = sum_tk E[tk][tq]*R[tk]; scale V (half) ----------
__global__ void __launch_bounds__(256, 2) colsum_e()
{
    __shared__ float Rs[TT];
    __shared__ float Cs[512];

    const int tid = threadIdx.x;
    const int bh = blockIdx.y, b = bh >> 4, h = bh & 15;
    const int tq0 = blockIdx.x * 512;

    #pragma unroll
    for (int j = 0; j < 8; j++) Rs[j * 256 + tid] = g_R[bh * TT + j * 256 + tid];
    if (tid < 128) { Cs[tid * 4] = 0.f; Cs[tid * 4 + 1] = 0.f;
                     Cs[tid * 4 + 2] = 0.f; Cs[tid * 4 + 3] = 0.f; }
    __syncthreads();

    const __half* Eb = g_E + (size_t)bh * TT * TT;
    const int g = tid >> 6;
    const int tqo = tq0 + (tid & 63) * 8;

    float acc[8];
    #pragma unroll
    for (int q = 0; q < 8; q++) acc[q] = 0.f;

    for (int tkb = g * 512; tkb < (g + 1) * 512; tkb += 4) {
        #pragma unroll
        for (int u = 0; u < 4; u++) {
            int tk = tkb + u;
            uint4 ev = *(const uint4*)&Eb[(size_t)tk * TT + tqo];
            float r = Rs[tk];
            const __half2* hp = (const __half2*)&ev;
            #pragma unroll
            for (int q = 0; q < 4; q++) {
                float2 f = __half22float2(hp[q]);
                acc[2 * q]     = fmaf(f.x, r, acc[2 * q]);
                acc[2 * q + 1] = fmaf(f.y, r, acc[2 * q + 1]);
            }
        }
    }

    #pragma unroll
    for (int q = 0; q < 8; q++)
        atomicAdd(&Cs[(tid & 63) * 8 + q], acc[q]);
    __syncthreads();

    for (int idx = tid; idx < 512 * 8; idx += 256) {
        int row = idx >> 3, c8 = (idx & 7) * 8;
        float s = Cs[row];
        __half* vp = &g_V[(size_t)(b * TT + tq0 + row) * DM + h * DD + c8];
        uint4 hv = *(uint4*)vp;
        __half2* hp = (__half2*)&hv;
        #pragma unroll
        for (int q = 0; q < 4; q++) {
            float2 f = __half22float2(hp[q]);
            hp[q] = __floats2half2_rn(f.x * s, f.y * s);
        }
        *(uint4*)vp = hv;
    }
}

// ---------------- launch -----------------------------------------------------
extern "C" void kernel_launch(void* const* d_in, const int* in_sizes, int n_in,
                              void* d_out, int out_size)
{
    const float* x  = (const float*)d_in[0];
    const float* Wq = (const float*)d_in[1];
    const float* bq = (const float*)d_in[2];
    const float* Wk = (const float*)d_in[3];
    const float* bk = (const float*)d_in[4];
    const float* Wv = (const float*)d_in[5];
    const float* bv = (const float*)d_in[6];
    const float* Wo = (const float*)d_in[7];
    const float* bo = (const float*)d_in[8];
    float* out = (float*)d_out;

    cudaFuncSetAttribute(gemm_qkv,
        cudaFuncAttributeMaxDynamicSharedMemorySize, GEMM_SMEM_BYTES);
    cudaFuncSetAttribute(gemm_out,
        cudaFuncAttributeMaxDynamicSharedMemorySize, GEMM_SMEM_BYTES);
    cudaFuncSetAttribute(attn_z_mma,
        cudaFuncAttributeMaxDynamicSharedMemorySize, ATTN_SMEM_BYTES);

    conv_x<<<(BT * DM) / 1024, 256>>>(x);
    conv_w4<<<dim3(DM / 32, DM / 32, 4), 256>>>(Wq, Wk, Wv, Wo);
    gemm_qkv<<<dim3(DM / 128, BT / 128, 3), 256, GEMM_SMEM_BYTES>>>(bq, bk, bv);
    attn_z_mma<<<dim3(TT / 128, BHD), 256, ATTN_SMEM_BYTES>>>();
    colsum_e<<<dim3(TT / 512, BHD), 256>>>();
    gemm_out<<<dim3(DM / 128, BT / 128), 256, GEMM_SMEM_BYTES>>>(bo, out);
}

// round 17
// speedup vs baseline: 6.3023x; 1.0843x over previous
#include <cuda_runtime.h>
#include <cuda_fp16.h>
#include <cstdint>

#define BB 2
#define TT 2048
#define HH 16
#define DD 64
#define DM 1024
#define BT (BB*TT)      // 4096
#define BHD (BB*HH)     // 32

// ---------------- static scratch ----------------
__device__ __half g_X [(size_t)BT*DM];      // 8 MB  x in fp16
__device__ __half g_Wq[(size_t)DM*DM];      // 2 MB  W^T in fp16 [n][k]
__device__ __half g_Wk[(size_t)DM*DM];
__device__ __half g_Wv[(size_t)DM*DM];
__device__ __half g_Wo[(size_t)DM*DM];
__device__ __half g_Q [(size_t)BT*DM];      // 8 MB
__device__ __half g_K [(size_t)BT*DM];      // 8 MB
__device__ __half g_V [(size_t)BT*DM];      // 8 MB
__device__ __half g_E [(size_t)BHD*TT*TT];  // 268 MB exp(s/8)
__device__ float  g_R [BHD*TT];             // 1/Z per (b,h,tk)

// ---------------- low-level helpers ----------------
__device__ __forceinline__ float ex2f(float x) {
    float r;
    asm("ex2.approx.f32 %0, %1;" : "=f"(r) : "f"(x));
    return r;
}
#define EXPS(s) ex2f((s) * 0.18033688011112042f)   // exp(s/8)

__device__ __forceinline__ void mma16(float c[4],
    uint32_t a0, uint32_t a1, uint32_t a2, uint32_t a3,
    uint32_t b0, uint32_t b1)
{
    asm volatile(
        "mma.sync.aligned.m16n8k16.row.col.f32.f16.f16.f32 "
        "{%0,%1,%2,%3}, {%4,%5,%6,%7}, {%8,%9}, {%0,%1,%2,%3};"
        : "+f"(c[0]), "+f"(c[1]), "+f"(c[2]), "+f"(c[3])
        : "r"(a0), "r"(a1), "r"(a2), "r"(a3), "r"(b0), "r"(b1));
}

__device__ __forceinline__ void ldsm4(uint32_t r[4], uint32_t addr) {
    asm volatile("ldmatrix.sync.aligned.m8n8.x4.shared.b16 {%0,%1,%2,%3}, [%4];"
        : "=r"(r[0]), "=r"(r[1]), "=r"(r[2]), "=r"(r[3]) : "r"(addr));
}

__device__ __forceinline__ void cp16(uint32_t smem_b, const void* g) {
    asm volatile("cp.async.ca.shared.global [%0], [%1], 16;"
                 :: "r"(smem_b), "l"(g));
}
#define CP_COMMIT() asm volatile("cp.async.commit_group;")
#define CP_WAIT1()  asm volatile("cp.async.wait_group 1;")

// ---- one-time conversions -------------------------------------------------
__global__ void __launch_bounds__(256) conv_x(const float* __restrict__ x)
{
    int i = (blockIdx.x * 256 + threadIdx.x) * 4;
    float4 v = *(const float4*)&x[i];
    *(__half2*)&g_X[i]     = __floats2half2_rn(v.x, v.y);
    *(__half2*)&g_X[i + 2] = __floats2half2_rn(v.z, v.w);
}

// Wt[n][k] = (half)W[k][n], all four weights in one launch (grid.z = which)
__global__ void __launch_bounds__(256) conv_w4(
    const float* __restrict__ W0, const float* __restrict__ W1,
    const float* __restrict__ W2, const float* __restrict__ W3)
{
    __shared__ float t[32][33];
    const float* src; __half* dst;
    switch (blockIdx.z) {
        case 0:  src = W0; dst = g_Wq; break;
        case 1:  src = W1; dst = g_Wk; break;
        case 2:  src = W2; dst = g_Wv; break;
        default: src = W3; dst = g_Wo; break;
    }
    const int nb = blockIdx.x * 32, kb = blockIdx.y * 32;
    const int tx = threadIdx.x & 31, ty = threadIdx.x >> 5;
    #pragma unroll
    for (int j = 0; j < 32; j += 8)
        t[ty + j][tx] = src[(size_t)(kb + ty + j) * DM + nb + tx];   // t[k][n]
    __syncthreads();
    #pragma unroll
    for (int j = 0; j < 32; j += 8)
        dst[(size_t)(nb + ty + j) * DM + kb + tx] = __float2half(t[tx][ty + j]);
}

// ================= fp16 gemm core, cp.async double-buffered, k-chunk 64 ====
#define GS 72                            // smem row stride in halves
#define G_TILE (128*GS)                  // halves per 128x64 tile
#define G_BUF  (2*G_TILE)                // A + B per buffer
#define GEMM_SMEM_BYTES (2*G_BUF*2)      // 73728 B

__device__ __forceinline__ void gemm_issue_chunk(
    uint32_t sb, int buf, const __half* __restrict__ A,
    const __half* __restrict__ Wt, int m0, int n0, int kb, int K, int tid)
{
    uint32_t base = sb + (uint32_t)buf * G_BUF * 2;
    #pragma unroll
    for (int j = 0; j < 4; j++) {           // A: 128 rows x 64 halves
        int pos = j * 256 + tid;            // 0..1023
        int row = pos >> 3, c8 = (pos & 7) * 8;
        cp16(base + (row * GS + c8) * 2,
             A + (size_t)(m0 + row) * K + kb + c8);
    }
    #pragma unroll
    for (int j = 0; j < 4; j++) {           // B: 128 n-rows x 64 halves
        int pos = j * 256 + tid;
        int row = pos >> 3, c8 = (pos & 7) * 8;
        cp16(base + (G_TILE + row * GS + c8) * 2,
             Wt + (size_t)(n0 + row) * K + kb + c8);
    }
}

__device__ __forceinline__ void gemm_core(
    const __half* __restrict__ A, const __half* __restrict__ Wt,
    const float* __restrict__ bias, __half* __restrict__ CoutH,
    float* __restrict__ CoutF, int M, int N, int K, int m0, int n0)
{
    extern __shared__ __half smem[];
    uint32_t sb = (uint32_t)__cvta_generic_to_shared(smem);

    const int tid = threadIdx.x, lane = tid & 31, wid = tid >> 5;
    const int grp = lane >> 2, t4 = lane & 3;
    const int lr = lane & 7, lq = lane >> 3;
    const int wm = wid >> 2, wn = wid & 3;

    float c[4][4][4];
    #pragma unroll
    for (int mi = 0; mi < 4; mi++)
        #pragma unroll
        for (int ni = 0; ni < 4; ni++)
            #pragma unroll
            for (int r = 0; r < 4; r++) c[mi][ni][r] = 0.f;

    const int nchunks = K / 64;
    gemm_issue_chunk(sb, 0, A, Wt, m0, n0, 0, K, tid);
    CP_COMMIT();
    gemm_issue_chunk(sb, 1, A, Wt, m0, n0, 64, K, tid);
    CP_COMMIT();

    const int a_row = lr + ((lq & 1) << 3);
    const int a_col = (lq >> 1) << 3;
    const int b_row = lr + ((lq >> 1) << 3);
    const int b_col = (lq & 1) << 3;

    for (int ci = 0; ci < nchunks; ci++) {
        const int buf = ci & 1;
        const uint32_t As = sb + (uint32_t)buf * G_BUF * 2;
        const uint32_t Bs = As + G_TILE * 2;
        CP_WAIT1();
        __syncthreads();

        #pragma unroll
        for (int ks = 0; ks < 4; ks++) {
            const int k0 = ks * 16;
            uint32_t a[4][4], b[2][4];
            #pragma unroll
            for (int mi = 0; mi < 4; mi++)
                ldsm4(a[mi], As + ((wm * 64 + mi * 16 + a_row) * GS + k0 + a_col) * 2);
            #pragma unroll
            for (int np = 0; np < 2; np++)
                ldsm4(b[np], Bs + ((wn * 32 + np * 16 + b_row) * GS + k0 + b_col) * 2);
            #pragma unroll
            for (int mi = 0; mi < 4; mi++)
                #pragma unroll
                for (int ni = 0; ni < 4; ni++)
                    mma16(c[mi][ni], a[mi][0], a[mi][1], a[mi][2], a[mi][3],
                          b[ni >> 1][(ni & 1) * 2], b[ni >> 1][(ni & 1) * 2 + 1]);
        }
        __syncthreads();
        if (ci + 2 < nchunks)
            gemm_issue_chunk(sb, buf, A, Wt, m0, n0, (ci + 2) * 64, K, tid);
        CP_COMMIT();
    }

    #pragma unroll
    for (int mi = 0; mi < 4; mi++) {
        int r0 = m0 + wm * 64 + mi * 16 + grp;
        #pragma unroll
        for (int ni = 0; ni < 4; ni++) {
            int cb = n0 + wn * 32 + ni * 8 + 2 * t4;
            float b0 = bias[cb], b1 = bias[cb + 1];
            float v00 = c[mi][ni][0] + b0, v01 = c[mi][ni][1] + b1;
            float v10 = c[mi][ni][2] + b0, v11 = c[mi][ni][3] + b1;
            if (CoutH) {
                *(__half2*)&CoutH[(size_t)r0 * N + cb]       = __floats2half2_rn(v00, v01);
                *(__half2*)&CoutH[(size_t)(r0 + 8) * N + cb] = __floats2half2_rn(v10, v11);
            } else {
                *(float2*)&CoutF[(size_t)r0 * N + cb]       = make_float2(v00, v01);
                *(float2*)&CoutF[(size_t)(r0 + 8) * N + cb] = make_float2(v10, v11);
            }
        }
    }
}

__global__ void __launch_bounds__(256, 2) gemm_qkv(
    const float* __restrict__ bq, const float* __restrict__ bk,
    const float* __restrict__ bv)
{
    const __half* Wt; const float* bias; __half* Cout;
    switch (blockIdx.z) {
        case 0:  Wt = g_Wq; bias = bq; Cout = g_Q; break;
        case 1:  Wt = g_Wk; bias = bk; Cout = g_K; break;
        default: Wt = g_Wv; bias = bv; Cout = g_V; break;
    }
    gemm_core(g_X, Wt, bias, Cout, nullptr, BT, DM, DM,
              blockIdx.y * 128, blockIdx.x * 128);
}

__global__ void __launch_bounds__(256, 2) gemm_out(
    const float* __restrict__ bo, float* __restrict__ out)
{
    gemm_core(g_V, g_Wo, bo, nullptr, out, BT, DM, DM,
              blockIdx.y * 128, blockIdx.x * 128);
}

// ================= attention pass 1 ========================================
#define A_STR  72
#define A_TILE (128*A_STR)               // 9216 halves per 128x64 tile
#define ES_STR 136                       // E staging row stride (halves)
#define ES_TILE (128*ES_STR)             // 17408 halves = 34816 B
#define ATTN_SMEM_BYTES ((3*A_TILE + ES_TILE + 512)*2)   // ~91 KB

__device__ __forceinline__ void attn_issue_tile(
    uint32_t sb, uint32_t off_halves, const __half* __restrict__ src,
    int row0, int tid)
{
    #pragma unroll
    for (int j = 0; j < 4; j++) {
        int pos = j * 256 + tid;
        int row = pos >> 3, d8 = (pos & 7) * 8;
        cp16(sb + (off_halves + row * A_STR + d8) * 2,
             src + (size_t)(row0 + row) * DM + d8);
    }
}

__device__ __forceinline__ void score_mma64(
    float c[4][4][4], uint32_t Ka, uint32_t Qb,
    int wm, int wn, int a_row, int a_col, int b_row, int b_col)
{
    #pragma unroll
    for (int ks = 0; ks < 4; ks++) {
        const int k0 = ks * 16;
        uint32_t a[4][4], b[2][4];
        #pragma unroll
        for (int mi = 0; mi < 4; mi++)
            ldsm4(a[mi], Ka + ((wm * 64 + mi * 16 + a_row) * A_STR + k0 + a_col) * 2);
        #pragma unroll
        for (int np = 0; np < 2; np++)
            ldsm4(b[np], Qb + ((wn * 32 + np * 16 + b_row) * A_STR + k0 + b_col) * 2);
        #pragma unroll
        for (int mi = 0; mi < 4; mi++)
            #pragma unroll
            for (int ni = 0; ni < 4; ni++)
                mma16(c[mi][ni], a[mi][0], a[mi][1], a[mi][2], a[mi][3],
                      b[ni >> 1][(ni & 1) * 2], b[ni >> 1][(ni & 1) * 2 + 1]);
    }
}

__global__ void __launch_bounds__(256, 2) attn_z_mma()
{
    extern __shared__ __half hsmem[];
    uint32_t sb = (uint32_t)__cvta_generic_to_shared(hsmem);
    __half* ES = hsmem + 3 * A_TILE;                 // E staging tile
    float* Zs = (float*)(hsmem + 3 * A_TILE + ES_TILE);

    const int tid = threadIdx.x, lane = tid & 31, wid = tid >> 5;
    const int grp = lane >> 2, t4 = lane & 3;
    const int lr = lane & 7, lq = lane >> 3;
    const int wm = wid >> 2, wn = wid & 3;
    const int bh = blockIdx.y, b = bh >> 4, h = bh & 15;
    const int tk0 = blockIdx.x * 128;

    const int a_row = lr + ((lq & 1) << 3), a_col = (lq >> 1) << 3;
    const int b_row = lr + ((lq >> 1) << 3), b_col = (lq & 1) << 3;

    const __half* Qb = g_Q + (size_t)b * TT * DM + h * DD;
    const __half* Kb = g_K + (size_t)b * TT * DM + h * DD;
    __half* Eb = g_E + (size_t)bh * TT * TT;

    if (tid < 128) Zs[tid] = 0.f;

    attn_issue_tile(sb, 0, Kb, tk0, tid);
    attn_issue_tile(sb, A_TILE, Qb, 0, tid);
    CP_COMMIT();
    attn_issue_tile(sb, 2 * A_TILE, Qb, 128, tid);
    CP_COMMIT();

    float zacc[4][2];
    #pragma unroll
    for (int mi = 0; mi < 4; mi++) { zacc[mi][0] = 0.f; zacc[mi][1] = 0.f; }

    for (int tqc = 0; tqc < 16; tqc++) {
        const int buf = tqc & 1;
        const uint32_t Qs = sb + (uint32_t)(1 + buf) * A_TILE * 2;
        CP_WAIT1();
        __syncthreads();

        float c[4][4][4];
        #pragma unroll
        for (int mi = 0; mi < 4; mi++)
            #pragma unroll
            for (int ni = 0; ni < 4; ni++)
                #pragma unroll
                for (int r = 0; r < 4; r++) c[mi][ni][r] = 0.f;

        score_mma64(c, sb, Qs, wm, wn, a_row, a_col, b_row, b_col);

        // exp + stage into smem (conflict-free 4B STS)
        #pragma unroll
        for (int mi = 0; mi < 4; mi++) {
            int r_l = wm * 64 + mi * 16 + grp;
            #pragma unroll
            for (int ni = 0; ni < 4; ni++) {
                int c_l = wn * 32 + ni * 8 + 2 * t4;
                float e0 = EXPS(c[mi][ni][0]), e1 = EXPS(c[mi][ni][1]);
                float e2 = EXPS(c[mi][ni][2]), e3 = EXPS(c[mi][ni][3]);
                zacc[mi][0] += e0 + e1;
                zacc[mi][1] += e2 + e3;
                *(__half2*)&ES[r_l * ES_STR + c_l]       = __floats2half2_rn(e0, e1);
                *(__half2*)&ES[(r_l + 8) * ES_STR + c_l] = __floats2half2_rn(e2, e3);
            }
        }
        __syncthreads();                 // staging complete; Qs reads done

        // coalesced 16B stores of the 128x128 E tile
        #pragma unroll
        for (int j = 0; j < 8; j++) {
            int pos = j * 256 + tid;     // 0..2047
            int row = pos >> 4, c16 = (pos & 15) * 8;
            *(uint4*)&Eb[(size_t)(tk0 + row) * TT + tqc * 128 + c16] =
                *(const uint4*)&ES[row * ES_STR + c16];
        }
        if (tqc + 2 < 16)
            attn_issue_tile(sb, (uint32_t)(1 + buf) * A_TILE, Qb, (tqc + 2) * 128, tid);
        CP_COMMIT();
    }

    #pragma unroll
    for (int mi = 0; mi < 4; mi++)
        #pragma unroll
        for (int hf = 0; hf < 2; hf++) {
            float v = zacc[mi][hf];
            v += __shfl_xor_sync(0xffffffffu, v, 1);
            v += __shfl_xor_sync(0xffffffffu, v, 2);
            if (t4 == 0) atomicAdd(&Zs[wm * 64 + mi * 16 + grp + hf * 8], v);
        }
    __syncthreads();
    if (tid < 128) g_R[bh * TT + tk0 + tid] = 1.0f / Zs[tid];
}

// ---- pass 2: colsum[tq] = sum_tk E[tk][tq]*R[tk]; scale V (half) ----------
__global__ void __launch_bounds__(256, 2) colsum_e()
{
    __shared__ float Rs[TT];
    __shared__ float Cs[512];

    const int tid = threadIdx.x;
    const int bh = blockIdx.y, b = bh >> 4, h = bh & 15;
    const int tq0 = blockIdx.x * 512;

    #pragma unroll
    for (int j = 0; j < 8; j++) Rs[j * 256 + tid] = g_R[bh * TT + j * 256 + tid];
    if (tid < 128) { Cs[tid * 4] = 0.f; Cs[tid * 4 + 1] = 0.f;
                     Cs[tid * 4 + 2] = 0.f; Cs[tid * 4 + 3] = 0.f; }
    __syncthreads();

    const __half* Eb = g_E + (size_t)bh * TT * TT;
    const int g = tid >> 6;
    const int tqo = tq0 + (tid & 63) * 8;

    float acc[8];
    #pragma unroll
    for (int q = 0; q < 8; q++) acc[q] = 0.f;

    for (int tkb = g * 512; tkb < (g + 1) * 512; tkb += 4) {
        #pragma unroll
        for (int u = 0; u < 4; u++) {
            int tk = tkb + u;
            uint4 ev = *(const uint4*)&Eb[(size_t)tk * TT + tqo];
            float r = Rs[tk];
            const __half2* hp = (const __half2*)&ev;
            #pragma unroll
            for (int q = 0; q < 4; q++) {
                float2 f = __half22float2(hp[q]);
                acc[2 * q]     = fmaf(f.x, r, acc[2 * q]);
                acc[2 * q + 1] = fmaf(f.y, r, acc[2 * q + 1]);
            }
        }
    }

    #pragma unroll
    for (int q = 0; q < 8; q++)
        atomicAdd(&Cs[(tid & 63) * 8 + q], acc[q]);
    __syncthreads();

    for (int idx = tid; idx < 512 * 8; idx += 256) {
        int row = idx >> 3, c8 = (idx & 7) * 8;
        float s = Cs[row];
        __half* vp = &g_V[(size_t)(b * TT + tq0 + row) * DM + h * DD + c8];
        uint4 hv = *(uint4*)vp;
        __half2* hp = (__half2*)&hv;
        #pragma unroll
        for (int q = 0; q < 4; q++) {
            float2 f = __half22float2(hp[q]);
            hp[q] = __floats2half2_rn(f.x * s, f.y * s);
        }
        *(uint4*)vp = hv;
    }
}

// ---------------- launch -----------------------------------------------------
extern "C" void kernel_launch(void* const* d_in, const int* in_sizes, int n_in,
                              void* d_out, int out_size)
{
    const float* x  = (const float*)d_in[0];
    const float* Wq = (const float*)d_in[1];
    const float* bq = (const float*)d_in[2];
    const float* Wk = (const float*)d_in[3];
    const float* bk = (const float*)d_in[4];
    const float* Wv = (const float*)d_in[5];
    const float* bv = (const float*)d_in[6];
    const float* Wo = (const float*)d_in[7];
    const float* bo = (const float*)d_in[8];
    float* out = (float*)d_out;

    cudaFuncSetAttribute(gemm_qkv,
        cudaFuncAttributeMaxDynamicSharedMemorySize, GEMM_SMEM_BYTES);
    cudaFuncSetAttribute(gemm_out,
        cudaFuncAttributeMaxDynamicSharedMemorySize, GEMM_SMEM_BYTES);
    cudaFuncSetAttribute(attn_z_mma,
        cudaFuncAttributeMaxDynamicSharedMemorySize, ATTN_SMEM_BYTES);

    conv_x<<<(BT * DM) / 1024, 256>>>(x);
    conv_w4<<<dim3(DM / 32, DM / 32, 4), 256>>>(Wq, Wk, Wv, Wo);
    gemm_qkv<<<dim3(DM / 128, BT / 128, 3), 256, GEMM_SMEM_BYTES>>>(bq, bk, bv);
    attn_z_mma<<<dim3(TT / 128, BHD), 256, ATTN_SMEM_BYTES>>>();
    colsum_e<<<dim3(TT / 512, BHD), 256>>>();
    gemm_out<<<dim3(DM / 128, BT / 128), 256, GEMM_SMEM_BYTES>>>(bo, out);
}